// round 15
// baseline (speedup 1.0000x reference)
#include <cuda_runtime.h>
#include <cuda_fp16.h>
#include <math.h>
#include <stdint.h>

#define CDIV(a,b) (((a)+(b)-1)/(b))

// ---------------- static scratch (no allocations allowed) ----------------
__device__ __half g_col1h[737280 * 32];
__device__ __half g_y1h [737280 * 64];
__device__ __half g_p1h [184320 * 64];
__device__ __half g_y2h [184320 * 64];
__device__ float  g_x   [46080 * 64];
__device__ __half g_xh  [46080 * 64];        // final x fp16 (for pcaps)
__device__ __half g_h16 [46080 * 64];
__device__ __half g_aoh [46080 * 768];
__device__ float  g_pc  [8192 * 256];
__device__ __half g_uh  [256 * 1024 * 48];
__device__ __half g_qh  [12 * 12 * 3 * 64 * 64];
__device__ __half g_owh [12 * 64 * 768];
__device__ __half g_w1h [12 * 256 * 64];
__device__ __half g_w2h [12 * 64 * 256];
__device__ __half g_cw1h[64 * 32];
__device__ __half g_cw2h[64 * 576];
__device__ __half g_cw3h[256 * 576];         // pcaps w [n][tap*64+ci]

// ---------------- weight prep ----------------
__global__ void prep_qkv_k(const float* __restrict__ qw, __half* __restrict__ qh) {
    int idx = blockIdx.x * 256 + threadIdx.x;
    if (idx >= 12 * 12 * 3 * 4096) return;
    int k = idx & 63, n = (idx >> 6) & 63;
    int rest = idx >> 12;
    int mat = rest % 3; rest /= 3;
    int h = rest % 12, l = rest / 12;
    int moff = (mat == 0) ? 768 : (mat == 1) ? 1536 : 0;
    qh[idx] = __float2half(qw[(long)l * 64 * 2304 + (long)k * 2304 + moff + h * 64 + n]);
}
__global__ void prep_ow_k(const float* __restrict__ ow, __half* __restrict__ oh) {
    int idx = blockIdx.x * 256 + threadIdx.x;
    if (idx >= 12 * 64 * 768) return;
    int k = idx % 768, n = (idx / 768) % 64, l = idx / 49152;
    oh[idx] = __float2half(ow[(long)l * 49152 + (long)k * 64 + n]);
}
__global__ void prep_w1_k(const float* __restrict__ w1, __half* __restrict__ o) {
    int idx = blockIdx.x * 256 + threadIdx.x;
    if (idx >= 12 * 256 * 64) return;
    int k = idx & 63, n = (idx >> 6) & 255, l = idx >> 14;
    o[idx] = __float2half(w1[(long)l * 16384 + (long)k * 256 + n]);
}
__global__ void prep_w2_k(const float* __restrict__ w2, __half* __restrict__ o) {
    int idx = blockIdx.x * 256 + threadIdx.x;
    if (idx >= 12 * 64 * 256) return;
    int k = idx & 255, n = (idx >> 8) & 63, l = idx >> 14;
    o[idx] = __float2half(w2[(long)l * 16384 + (long)k * 64 + n]);
}
__global__ void prep_cw1_k(const float* __restrict__ w, __half* __restrict__ o) {
    int idx = blockIdx.x * 256 + threadIdx.x;
    if (idx >= 64 * 32) return;
    int k = idx & 31, n = idx >> 5;
    o[idx] = __float2half(k < 27 ? w[n * 27 + k] : 0.f);
}
// conv2/pcaps: o[n*576 + tap*64 + ci] = w[n*576 + ci*9 + tap]
__global__ void prep_cwhwc_k(const float* __restrict__ w, __half* __restrict__ o, int N) {
    int idx = blockIdx.x * 256 + threadIdx.x;
    if (idx >= N * 576) return;
    int kk = idx % 576, n = idx / 576;
    int ci = kk & 63, tap = kk >> 6;
    o[idx] = __float2half(w[n * 576 + ci * 9 + tap]);
}

// ---------------- im2col (conv1 only) ----------------
__global__ void im2col1h_k(const float* __restrict__ x, __half* __restrict__ col) {
    long idx = (long)blockIdx.x * blockDim.x + threadIdx.x;
    const long total = (long)737280 * 32;
    if (idx >= total) return;
    int kk = (int)(idx & 31);
    long m = idx >> 5;
    if (kk >= 27) { col[idx] = __float2half(0.f); return; }
    int ow = (int)(m % 72);
    int t  = (int)(m / 72);
    int oh = t % 40;
    int b  = t / 40;
    int kw = kk % 3, kh = (kk / 3) % 3, ci = kk / 9;
    int ih = oh + kh - 1, iw = ow + kw - 1;
    float v = 0.f;
    if (ih >= 0 && ih < 40 && iw >= 0 && iw < 72)
        v = x[(((long)b * 3 + ci) * 40 + ih) * 72 + iw];
    col[idx] = __float2half(v);
}

// ---------------- fp16 mma helpers ----------------
__device__ __forceinline__ uint32_t smem_u32(const void* p) {
    return (uint32_t)__cvta_generic_to_shared(p);
}
__device__ __forceinline__ void ldsm_x4(uint32_t r[4], uint32_t addr) {
    asm volatile("ldmatrix.sync.aligned.m8n8.x4.shared.b16 {%0,%1,%2,%3}, [%4];"
        : "=r"(r[0]), "=r"(r[1]), "=r"(r[2]), "=r"(r[3]) : "r"(addr));
}
__device__ __forceinline__ void ldsm_x2(uint32_t r[2], uint32_t addr) {
    asm volatile("ldmatrix.sync.aligned.m8n8.x2.shared.b16 {%0,%1}, [%2];"
        : "=r"(r[0]), "=r"(r[1]) : "r"(addr));
}
__device__ __forceinline__ void ldsm_x4t(uint32_t r[4], uint32_t addr) {
    asm volatile("ldmatrix.sync.aligned.m8n8.x4.trans.shared.b16 {%0,%1,%2,%3}, [%4];"
        : "=r"(r[0]), "=r"(r[1]), "=r"(r[2]), "=r"(r[3]) : "r"(addr));
}
__device__ __forceinline__ void mma_f16(float d[4], const uint32_t a[4], const uint32_t b[2],
                                        const float c[4]) {
    asm volatile("mma.sync.aligned.m16n8k16.row.col.f32.f16.f16.f32 "
        "{%0,%1,%2,%3},{%4,%5,%6,%7},{%8,%9},{%10,%11,%12,%13};"
        : "=f"(d[0]), "=f"(d[1]), "=f"(d[2]), "=f"(d[3])
        : "r"(a[0]), "r"(a[1]), "r"(a[2]), "r"(a[3]), "r"(b[0]), "r"(b[1]),
          "f"(c[0]), "f"(c[1]), "f"(c[2]), "f"(c[3]));
}
__device__ __forceinline__ uint32_t packh2(float a, float b) {
    __half2 h = __floats2half2_rn(a, b);
    return *(uint32_t*)&h;
}

// ---------------- conv1 fp16 GEMM ----------------
#define HC1_SMEM ((64 * 40 + 128 * 40) * 2)
__global__ void __launch_bounds__(256) hconv1_k(const __half* __restrict__ col,
                                                const __half* __restrict__ wch,
                                                __half* __restrict__ y1) {
    extern __shared__ __half sm1[];
    __half* Ws = sm1;
    __half* As = sm1 + 64 * 40;

    const int bm = blockIdx.x * 128;
    const int tid = threadIdx.x, lane = tid & 31, w = tid >> 5;
    const int g4 = lane >> 2, c4 = lane & 3;
    const int lmrow = lane & 15, lmk = (lane >> 4) * 8;
    const int b2row = lane & 7, b2k = ((lane >> 3) & 1) * 8;
    const int r0 = w * 16;

    for (int idx = tid; idx < 64 * 4; idx += 256) {
        int n = idx >> 2, q = idx & 3;
        *(uint4*)&Ws[n * 40 + q * 8] = *(const uint4*)(wch + n * 32 + q * 8);
    }
    __syncthreads();

    const int ar = tid >> 1, apart = (tid & 1) * 16;
    {
        const uint4* src = (const uint4*)(col + (long)(bm + ar) * 32 + apart);
        uint4* dst = (uint4*)&As[ar * 40 + apart];
        dst[0] = src[0]; dst[1] = src[1];
    }
    __syncwarp();

    uint32_t afr[2][4];
#pragma unroll
    for (int ks = 0; ks < 2; ks++)
        ldsm_x4(afr[ks], smem_u32(&As[(r0 + lmrow) * 40 + ks * 16 + lmk]));

#pragma unroll
    for (int nt = 0; nt < 8; nt++) {
        float acc[4] = {0.f, 0.f, 0.f, 0.f};
#pragma unroll
        for (int ks = 0; ks < 2; ks++) {
            uint32_t bf[2];
            ldsm_x2(bf, smem_u32(&Ws[(nt * 8 + b2row) * 40 + ks * 16 + b2k]));
            mma_f16(acc, afr[ks], bf, acc);
        }
        int coln = nt * 8 + 2 * c4;
#pragma unroll
        for (int half = 0; half < 2; half++) {
            long row = bm + r0 + g4 + 8 * half;
            *(uint32_t*)(y1 + row * 64 + coln) =
                packh2(fmaxf(acc[2 * half], 0.f), fmaxf(acc[2 * half + 1], 0.f));
        }
    }
}

// ---------------- conv2 direct (fused im2col) ----------------
#define HC2_SMEM (64 * 584 * 2 + 128 * 72 * 2)
__global__ void __launch_bounds__(256) hconv2_k(const __half* __restrict__ p1,
                                                const __half* __restrict__ wch,
                                                __half* __restrict__ y2) {
    extern __shared__ __half smc[];
    __half* Ws = smc;
    __half* As = smc + 64 * 584;

    const int bm = blockIdx.x * 128;
    const int tid = threadIdx.x, lane = tid & 31, w = tid >> 5;
    const int g4 = lane >> 2, c4 = lane & 3;
    const int lmrow = lane & 15, lmk = (lane >> 4) * 8;
    const int m4 = lane >> 3, r8 = lane & 7;
    const int xrow = ((m4 >> 1) << 3) + r8, xk = (m4 & 1) * 8;
    const int r0 = w * 16;

    for (int idx = tid; idx < 64 * 72; idx += 256) {
        int n = idx / 72, q = idx % 72;
        *(uint4*)&Ws[n * 584 + q * 8] = *(const uint4*)(wch + n * 576 + q * 8);
    }
    __syncthreads();

    float acc[8][4];
#pragma unroll
    for (int nt = 0; nt < 8; nt++)
#pragma unroll
        for (int i = 0; i < 4; i++) acc[nt][i] = 0.f;

    const int ar = tid >> 1, apart = (tid & 1) * 32;
    const int m = bm + ar;
    const int bidx = m / 720, rem = m % 720;
    const int oh = rem / 36, owp = rem % 36;

#pragma unroll
    for (int kc = 0; kc < 9; kc++) {
        int kh = kc / 3, kw = kc % 3;
        int ih = oh + kh - 1, iw = owp + kw - 1;
        uint4 v[4];
        if ((unsigned)ih < 20u && (unsigned)iw < 36u) {
            const uint4* src = (const uint4*)(p1 + (((long)(bidx * 20 + ih)) * 36 + iw) * 64 + apart);
            v[0] = src[0]; v[1] = src[1]; v[2] = src[2]; v[3] = src[3];
        } else {
            v[0] = make_uint4(0, 0, 0, 0); v[1] = v[0]; v[2] = v[0]; v[3] = v[0];
        }
        uint4* dst = (uint4*)&As[ar * 72 + apart];
        dst[0] = v[0]; dst[1] = v[1]; dst[2] = v[2]; dst[3] = v[3];
        __syncwarp();
        uint32_t afr[4][4];
#pragma unroll
        for (int ks = 0; ks < 4; ks++)
            ldsm_x4(afr[ks], smem_u32(&As[(r0 + lmrow) * 72 + ks * 16 + lmk]));
#pragma unroll
        for (int ntp = 0; ntp < 4; ntp++) {
#pragma unroll
            for (int ks = 0; ks < 4; ks++) {
                uint32_t bf4[4];
                ldsm_x4(bf4, smem_u32(&Ws[(ntp * 16 + xrow) * 584 + kc * 64 + ks * 16 + xk]));
                mma_f16(acc[2 * ntp], afr[ks], bf4, acc[2 * ntp]);
                mma_f16(acc[2 * ntp + 1], afr[ks], bf4 + 2, acc[2 * ntp + 1]);
            }
        }
        __syncwarp();
    }

#pragma unroll
    for (int nt = 0; nt < 8; nt++) {
        int col = nt * 8 + 2 * c4;
#pragma unroll
        for (int half = 0; half < 2; half++) {
            long row = bm + r0 + g4 + 8 * half;
            *(uint32_t*)(y2 + row * 64 + col) =
                packh2(fmaxf(acc[nt][2 * half], 0.f), fmaxf(acc[nt][2 * half + 1], 0.f));
        }
    }
}

// ---------------- pcaps conv direct (fused im2col), N split in 2 halves ----------------
// x viewed as (B,10,18,64), conv k3 s2 p0 -> (B,4,8,256); pc fp32 +bias.
#define HC3_SMEM (128 * 584 * 2 + 128 * 72 * 2)
__global__ void __launch_bounds__(256) hconv3_k(const __half* __restrict__ xh,
                                                const __half* __restrict__ wch,
                                                const float* __restrict__ bias,
                                                float* __restrict__ pc) {
    extern __shared__ __half sm3[];
    __half* Ws = sm3;                 // [128 n][584 k]
    __half* As = sm3 + 128 * 584;     // [128 m][72]

    const int nh = blockIdx.x;        // n-half: 0 or 1
    const int bm = blockIdx.y * 128;
    const int tid = threadIdx.x, lane = tid & 31, w = tid >> 5;
    const int g4 = lane >> 2, c4 = lane & 3;
    const int lmrow = lane & 15, lmk = (lane >> 4) * 8;
    const int m4 = lane >> 3, r8 = lane & 7;
    const int xrow = ((m4 >> 1) << 3) + r8, xk = (m4 & 1) * 8;
    const int r0 = w * 16;

    const __half* wsrc = wch + (long)nh * 128 * 576;
    for (int idx = tid; idx < 128 * 72; idx += 256) {
        int n = idx / 72, q = idx % 72;
        *(uint4*)&Ws[n * 584 + q * 8] = *(const uint4*)(wsrc + n * 576 + q * 8);
    }
    __syncthreads();

    float acc[16][4];
#pragma unroll
    for (int nt = 0; nt < 16; nt++)
#pragma unroll
        for (int i = 0; i < 4; i++) acc[nt][i] = 0.f;

    const int ar = tid >> 1, apart = (tid & 1) * 32;
    const int m = bm + ar;
    const int bidx = m >> 5, rem = m & 31;
    const int oh = rem >> 3, owp = rem & 7;

#pragma unroll
    for (int kc = 0; kc < 9; kc++) {
        int kh = kc / 3, kw = kc % 3;
        int ih = oh * 2 + kh, iw = owp * 2 + kw;   // always in bounds (no pad)
        {
            const uint4* src = (const uint4*)(xh + ((long)bidx * 180 + ih * 18 + iw) * 64 + apart);
            uint4* dst = (uint4*)&As[ar * 72 + apart];
            dst[0] = src[0]; dst[1] = src[1]; dst[2] = src[2]; dst[3] = src[3];
        }
        __syncwarp();
        uint32_t afr[4][4];
#pragma unroll
        for (int ks = 0; ks < 4; ks++)
            ldsm_x4(afr[ks], smem_u32(&As[(r0 + lmrow) * 72 + ks * 16 + lmk]));
#pragma unroll
        for (int ntp = 0; ntp < 8; ntp++) {
#pragma unroll
            for (int ks = 0; ks < 4; ks++) {
                uint32_t bf4[4];
                ldsm_x4(bf4, smem_u32(&Ws[(ntp * 16 + xrow) * 584 + kc * 64 + ks * 16 + xk]));
                mma_f16(acc[2 * ntp], afr[ks], bf4, acc[2 * ntp]);
                mma_f16(acc[2 * ntp + 1], afr[ks], bf4 + 2, acc[2 * ntp + 1]);
            }
        }
        __syncwarp();
    }

#pragma unroll
    for (int nt = 0; nt < 16; nt++) {
        int gcol = nh * 128 + nt * 8 + 2 * c4;
        float b0 = bias[gcol], b1 = bias[gcol + 1];
#pragma unroll
        for (int half = 0; half < 2; half++) {
            long row = bm + r0 + g4 + 8 * half;
            *(float2*)(pc + row * 256 + gcol) =
                make_float2(acc[nt][2 * half] + b0, acc[nt][2 * half + 1] + b1);
        }
    }
}

// ---------------- maxpool ----------------
template <typename Ti, typename To>
__global__ void maxpool_k(const Ti* __restrict__ in, To* __restrict__ out,
                          int Bn, int IH, int IW, int C, int OH, int OW,
                          const float* __restrict__ pos) {
    long idx = (long)blockIdx.x * blockDim.x + threadIdx.x;
    long total = (long)Bn * OH * OW * C;
    if (idx >= total) return;
    int c = (int)(idx % C);
    long r = idx / C;
    int ow = (int)(r % OW); r /= OW;
    int oh = (int)(r % OH);
    int b  = (int)(r / OH);
    float m = -1e30f;
#pragma unroll
    for (int kh = 0; kh < 3; kh++) {
        int ih = oh * 2 - 1 + kh;
        if (ih < 0 || ih >= IH) continue;
#pragma unroll
        for (int kw = 0; kw < 3; kw++) {
            int iw = ow * 2 - 1 + kw;
            if (iw < 0 || iw >= IW) continue;
            m = fmaxf(m, (float)in[(((long)b * IH + ih) * IW + iw) * C + c]);
        }
    }
    if (pos) m += pos[(oh * OW + ow) * C + c];
    out[idx] = (To)m;
}

// ---------------- LN1 -> fp16 (layer 0 only) ----------------
__global__ void ln1h_k(const float* __restrict__ x, const float* __restrict__ g,
                       const float* __restrict__ bta, __half* __restrict__ o, int ntok) {
    int warp = (blockIdx.x * blockDim.x + threadIdx.x) >> 5;
    int lane = threadIdx.x & 31;
    if (warp >= ntok) return;
    float v0 = x[(long)warp * 64 + lane];
    float v1 = x[(long)warp * 64 + 32 + lane];
    float s = v0 + v1;
#pragma unroll
    for (int off = 16; off; off >>= 1) s += __shfl_xor_sync(0xffffffffu, s, off);
    float mean = s * (1.f / 64.f);
    float d0 = v0 - mean, d1 = v1 - mean;
    float q = d0 * d0 + d1 * d1;
#pragma unroll
    for (int off = 16; off; off >>= 1) q += __shfl_xor_sync(0xffffffffu, q, off);
    float rstd = rsqrtf(q * (1.f / 64.f) + 1e-5f);
    o[(long)warp * 64 + lane]      = __float2half(d0 * rstd * g[lane] + bta[lane]);
    o[(long)warp * 64 + 32 + lane] = __float2half(d1 * rstd * g[lane + 32] + bta[lane + 32]);
}

// ---------------- fully-fused attention (x4 ldsm) ----------------
#define ATTNH_SMEM ((3 * 192 * 72 + 3 * 64 * 72) * 2)

__global__ void __launch_bounds__(384, 1) attn_fused_k(const __half* __restrict__ h16g,
                                                       const __half* __restrict__ qh,
                                                       __half* __restrict__ out) {
    extern __shared__ __half smh[];
    __half* H16 = smh;
    __half* K16 = smh + 192 * 72;
    __half* V16 = smh + 2 * 192 * 72;
    __half* W16 = smh + 3 * 192 * 72;

    int b = blockIdx.x / 12, h = blockIdx.x % 12;
    int tid = threadIdx.x, lane = tid & 31, w = tid >> 5;
    int g4 = lane >> 2, c4 = lane & 3;
    int lmrow = lane & 15, lmk = (lane >> 4) * 8;
    int m4 = lane >> 3, r8 = lane & 7;
    int xrow = ((m4 >> 1) << 3) + r8, xk = (m4 & 1) * 8;
    int trow = m4 * 8 + r8;
    const int r0 = w * 16;

    {
        const __half* qsrc = qh + (long)h * 12288;
        for (int idx = tid; idx < 192 * 8; idx += 384) {
            int row = idx >> 3, q = idx & 7;
            *(uint4*)&W16[row * 72 + q * 8] = *(const uint4*)(qsrc + row * 64 + q * 8);
        }
    }
    {
        const __half* hb = h16g + (long)b * 180 * 64;
        for (int idx = tid; idx < 180 * 8; idx += 384) {
            int row = idx >> 3, q = idx & 7;
            *(uint4*)&H16[row * 72 + q * 8] = *(const uint4*)(hb + row * 64 + q * 8);
        }
        for (int i = tid; i < 12 * 72; i += 384) H16[180 * 72 + i] = __float2half(0.f);
    }
    __syncthreads();

    uint32_t afr[4][4];
#pragma unroll
    for (int ks = 0; ks < 4; ks++)
        ldsm_x4(afr[ks], smem_u32(&H16[(r0 + lmrow) * 72 + ks * 16 + lmk]));

#pragma unroll
    for (int mat = 0; mat < 2; mat++) {
        const __half* Wm = W16 + mat * 64 * 72;
        __half* dst = mat ? V16 : K16;
#pragma unroll
        for (int ntp = 0; ntp < 4; ntp++) {
            float a0[4] = {0.f, 0.f, 0.f, 0.f}, a1[4] = {0.f, 0.f, 0.f, 0.f};
#pragma unroll
            for (int ks = 0; ks < 4; ks++) {
                uint32_t bf4[4];
                ldsm_x4(bf4, smem_u32(&Wm[(ntp * 16 + xrow) * 72 + ks * 16 + xk]));
                mma_f16(a0, afr[ks], bf4, a0);
                mma_f16(a1, afr[ks], bf4 + 2, a1);
            }
            int col0 = (2 * ntp) * 8 + 2 * c4, col1 = col0 + 8;
            *(uint32_t*)&dst[(r0 + g4) * 72 + col0]     = packh2(a0[0], a0[1]);
            *(uint32_t*)&dst[(r0 + g4 + 8) * 72 + col0] = packh2(a0[2], a0[3]);
            *(uint32_t*)&dst[(r0 + g4) * 72 + col1]     = packh2(a1[0], a1[1]);
            *(uint32_t*)&dst[(r0 + g4 + 8) * 72 + col1] = packh2(a1[2], a1[3]);
        }
    }

    uint32_t afq[4][4];
    {
        const __half* Wm = W16 + 2 * 64 * 72;
        float qacc[8][4];
#pragma unroll
        for (int ntp = 0; ntp < 4; ntp++) {
#pragma unroll
            for (int i = 0; i < 4; i++) { qacc[2 * ntp][i] = 0.f; qacc[2 * ntp + 1][i] = 0.f; }
#pragma unroll
            for (int ks = 0; ks < 4; ks++) {
                uint32_t bf4[4];
                ldsm_x4(bf4, smem_u32(&Wm[(ntp * 16 + xrow) * 72 + ks * 16 + xk]));
                mma_f16(qacc[2 * ntp], afr[ks], bf4, qacc[2 * ntp]);
                mma_f16(qacc[2 * ntp + 1], afr[ks], bf4 + 2, qacc[2 * ntp + 1]);
            }
        }
#pragma unroll
        for (int kt = 0; kt < 4; kt++) {
            afq[kt][0] = packh2(qacc[2 * kt][0],     qacc[2 * kt][1]);
            afq[kt][1] = packh2(qacc[2 * kt][2],     qacc[2 * kt][3]);
            afq[kt][2] = packh2(qacc[2 * kt + 1][0], qacc[2 * kt + 1][1]);
            afq[kt][3] = packh2(qacc[2 * kt + 1][2], qacc[2 * kt + 1][3]);
        }
    }
    __syncthreads();

    float S[24][4];
#pragma unroll
    for (int ntp = 0; ntp < 12; ntp++) {
        float a0[4] = {0.f, 0.f, 0.f, 0.f}, a1[4] = {0.f, 0.f, 0.f, 0.f};
#pragma unroll
        for (int ks = 0; ks < 4; ks++) {
            uint32_t bf4[4];
            ldsm_x4(bf4, smem_u32(&K16[(ntp * 16 + xrow) * 72 + ks * 16 + xk]));
            mma_f16(a0, afq[ks], bf4, a0);
            mma_f16(a1, afq[ks], bf4 + 2, a1);
        }
#pragma unroll
        for (int i = 0; i < 4; i++) {
            S[2 * ntp][i]     = a0[i] * 0.125f;
            S[2 * ntp + 1][i] = a1[i] * 0.125f;
        }
    }

    {
        float mx0 = -1e30f, mx1 = -1e30f;
#pragma unroll
        for (int nt = 0; nt < 24; nt++) {
#pragma unroll
            for (int j = 0; j < 2; j++) {
                int col = nt * 8 + 2 * c4 + j;
                if (col < 180) {
                    mx0 = fmaxf(mx0, S[nt][j]);
                    mx1 = fmaxf(mx1, S[nt][2 + j]);
                }
            }
        }
        mx0 = fmaxf(mx0, __shfl_xor_sync(0xffffffffu, mx0, 1));
        mx0 = fmaxf(mx0, __shfl_xor_sync(0xffffffffu, mx0, 2));
        mx1 = fmaxf(mx1, __shfl_xor_sync(0xffffffffu, mx1, 1));
        mx1 = fmaxf(mx1, __shfl_xor_sync(0xffffffffu, mx1, 2));
        float sum0 = 0.f, sum1 = 0.f;
#pragma unroll
        for (int nt = 0; nt < 24; nt++) {
#pragma unroll
            for (int j = 0; j < 2; j++) {
                int col = nt * 8 + 2 * c4 + j;
                float e0 = (col < 180) ? __expf(S[nt][j] - mx0) : 0.f;
                float e1 = (col < 180) ? __expf(S[nt][2 + j] - mx1) : 0.f;
                S[nt][j] = e0; S[nt][2 + j] = e1;
                sum0 += e0; sum1 += e1;
            }
        }
        sum0 += __shfl_xor_sync(0xffffffffu, sum0, 1);
        sum0 += __shfl_xor_sync(0xffffffffu, sum0, 2);
        sum1 += __shfl_xor_sync(0xffffffffu, sum1, 1);
        sum1 += __shfl_xor_sync(0xffffffffu, sum1, 2);
        float inv0 = 1.f / sum0, inv1 = 1.f / sum1;
#pragma unroll
        for (int nt = 0; nt < 24; nt++) {
            S[nt][0] *= inv0; S[nt][1] *= inv0;
            S[nt][2] *= inv1; S[nt][3] *= inv1;
        }
    }

    uint32_t P[12][4];
#pragma unroll
    for (int kt = 0; kt < 12; kt++) {
        P[kt][0] = packh2(S[2 * kt][0],     S[2 * kt][1]);
        P[kt][1] = packh2(S[2 * kt][2],     S[2 * kt][3]);
        P[kt][2] = packh2(S[2 * kt + 1][0], S[2 * kt + 1][1]);
        P[kt][3] = packh2(S[2 * kt + 1][2], S[2 * kt + 1][3]);
    }

    {
        __half* outb = out + (long)b * 180 * 768 + h * 64;
#pragma unroll
        for (int nt = 0; nt < 8; nt++) {
            float acc[4] = {0.f, 0.f, 0.f, 0.f};
#pragma unroll
            for (int ktp = 0; ktp < 6; ktp++) {
                uint32_t bv4[4];
                ldsm_x4t(bv4, smem_u32(&V16[(ktp * 32 + trow) * 72 + nt * 8]));
                mma_f16(acc, P[2 * ktp], bv4, acc);
                mma_f16(acc, P[2 * ktp + 1], bv4 + 2, acc);
            }
            int row = r0 + g4;
            long col = nt * 8 + 2 * c4;
            if (row < 180)
                *(uint32_t*)(outb + (long)row * 768 + col) = packh2(acc[0], acc[1]);
            if (row + 8 < 180)
                *(uint32_t*)(outb + (long)(row + 8) * 768 + col) = packh2(acc[2], acc[3]);
        }
    }
}

// ---------------- fused tail (x4 ldsm): outproj + LN2 + MLP + next LN1 (+fp16 x out) ----------------
#define T_WS   0
#define T_ASHS 49664
#define T_W1S  58880
#define T_W2S  77312
#define TAIL_SMEM 188416

__global__ void __launch_bounds__(256) tail_fused_k(const __half* __restrict__ ao,
                                                    const __half* __restrict__ owh,
                                                    const float* __restrict__ ob,
                                                    const float* __restrict__ x,
                                                    const __half* __restrict__ w1h,
                                                    const float* __restrict__ b1,
                                                    const __half* __restrict__ w2h,
                                                    const float* __restrict__ b2,
                                                    const float* __restrict__ lng,
                                                    const float* __restrict__ lnb,
                                                    float* __restrict__ outx,
                                                    const float* __restrict__ lng1n,
                                                    const float* __restrict__ lnb1n,
                                                    __half* __restrict__ h16out,
                                                    __half* __restrict__ xhout) {
    extern __shared__ __half smt[];
    __half* Ws  = smt + T_WS;
    __half* As  = smt + T_ASHS;
    __half* W1s = smt + T_W1S;
    __half* W2s = smt + T_W2S;

    const int tid = threadIdx.x, lane = tid & 31, w = tid >> 5;
    const int g4 = lane >> 2, c4 = lane & 3;
    const int lmrow = lane & 15, lmk = (lane >> 4) * 8;
    const int m4 = lane >> 3, r8 = lane & 7;
    const int xrow = ((m4 >> 1) << 3) + r8, xk = (m4 & 1) * 8;
    const int r0 = w * 16;

    for (int idx = tid; idx < 64 * 96; idx += 256) {
        int n = idx / 96, q = idx % 96;
        *(uint4*)&Ws[n * 776 + q * 8] = *(const uint4*)(owh + n * 768 + q * 8);
    }
    for (int idx = tid; idx < 256 * 8; idx += 256) {
        int n = idx >> 3, q = idx & 7;
        *(uint4*)&W1s[n * 72 + q * 8] = *(const uint4*)(w1h + n * 64 + q * 8);
    }
    for (int idx = tid; idx < 64 * 32; idx += 256) {
        int n = idx >> 5, q = idx & 31;
        *(uint4*)&W2s[n * 264 + q * 8] = *(const uint4*)(w2h + n * 256 + q * 8);
    }
    __syncthreads();

    const int ar = tid >> 1, apart = (tid & 1) * 32;

    for (int c = 0; c < 3; c++) {
        const long bm = ((long)blockIdx.x * 3 + c) * 128;

        float acc[8][4];
#pragma unroll
        for (int nt = 0; nt < 8; nt++)
#pragma unroll
            for (int i = 0; i < 4; i++) acc[nt][i] = 0.f;

        for (int kc = 0; kc < 12; kc++) {
            {
                const uint4* src = (const uint4*)(ao + (bm + ar) * 768 + kc * 64 + apart);
                uint4* dst = (uint4*)&As[ar * 72 + apart];
                dst[0] = src[0]; dst[1] = src[1]; dst[2] = src[2]; dst[3] = src[3];
            }
            __syncwarp();
            uint32_t afr[4][4];
#pragma unroll
            for (int ks = 0; ks < 4; ks++)
                ldsm_x4(afr[ks], smem_u32(&As[(r0 + lmrow) * 72 + ks * 16 + lmk]));
#pragma unroll
            for (int ntp = 0; ntp < 4; ntp++) {
#pragma unroll
                for (int ks = 0; ks < 4; ks++) {
                    uint32_t bf4[4];
                    ldsm_x4(bf4, smem_u32(&Ws[(ntp * 16 + xrow) * 776 + kc * 64 + ks * 16 + xk]));
                    mma_f16(acc[2 * ntp], afr[ks], bf4, acc[2 * ntp]);
                    mma_f16(acc[2 * ntp + 1], afr[ks], bf4 + 2, acc[2 * ntp + 1]);
                }
            }
            __syncwarp();
        }

        float xres[8][4];
#pragma unroll
        for (int nt = 0; nt < 8; nt++) {
            int col = nt * 8 + 2 * c4;
            float b0 = ob[col], b1v = ob[col + 1];
#pragma unroll
            for (int half = 0; half < 2; half++) {
                long row = bm + r0 + g4 + 8 * half;
                float2 r = *(const float2*)(x + row * 64 + col);
                xres[nt][2 * half]     = acc[nt][2 * half] + b0 + r.x;
                xres[nt][2 * half + 1] = acc[nt][2 * half + 1] + b1v + r.y;
            }
        }
        {
            float s0 = 0.f, s1 = 0.f;
#pragma unroll
            for (int nt = 0; nt < 8; nt++) {
                s0 += xres[nt][0] + xres[nt][1];
                s1 += xres[nt][2] + xres[nt][3];
            }
            s0 += __shfl_xor_sync(0xffffffffu, s0, 1);
            s0 += __shfl_xor_sync(0xffffffffu, s0, 2);
            s1 += __shfl_xor_sync(0xffffffffu, s1, 1);
            s1 += __shfl_xor_sync(0xffffffffu, s1, 2);
            float m0 = s0 * (1.f / 64.f), m1 = s1 * (1.f / 64.f);
            float q0 = 0.f, q1 = 0.f;
#pragma unroll
            for (int nt = 0; nt < 8; nt++) {
                float d0 = xres[nt][0] - m0, d1 = xres[nt][1] - m0;
                float d2 = xres[nt][2] - m1, d3 = xres[nt][3] - m1;
                q0 += d0 * d0 + d1 * d1;
                q1 += d2 * d2 + d3 * d3;
            }
            q0 += __shfl_xor_sync(0xffffffffu, q0, 1);
            q0 += __shfl_xor_sync(0xffffffffu, q0, 2);
            q1 += __shfl_xor_sync(0xffffffffu, q1, 1);
            q1 += __shfl_xor_sync(0xffffffffu, q1, 2);
            float rs0 = rsqrtf(q0 * (1.f / 64.f) + 1e-5f);
            float rs1 = rsqrtf(q1 * (1.f / 64.f) + 1e-5f);
#pragma unroll
            for (int nt = 0; nt < 8; nt++) {
                int col = nt * 8 + 2 * c4;
                float g0 = lng[col], g1 = lng[col + 1];
                float be0 = lnb[col], be1 = lnb[col + 1];
                float h0 = (xres[nt][0] - m0) * rs0 * g0 + be0;
                float h1 = (xres[nt][1] - m0) * rs0 * g1 + be1;
                float h2 = (xres[nt][2] - m1) * rs1 * g0 + be0;
                float h3 = (xres[nt][3] - m1) * rs1 * g1 + be1;
                *(uint32_t*)&As[(r0 + g4) * 72 + col]     = packh2(h0, h1);
                *(uint32_t*)&As[(r0 + g4 + 8) * 72 + col] = packh2(h2, h3);
            }
        }
        __syncwarp();

        uint32_t afg[16][4];
        {
            uint32_t afr[4][4];
#pragma unroll
            for (int ks = 0; ks < 4; ks++)
                ldsm_x4(afr[ks], smem_u32(&As[(r0 + lmrow) * 72 + ks * 16 + lmk]));
#pragma unroll
            for (int kt = 0; kt < 16; kt++) {
                float d0[4] = {0.f, 0.f, 0.f, 0.f}, d1[4] = {0.f, 0.f, 0.f, 0.f};
#pragma unroll
                for (int ks = 0; ks < 4; ks++) {
                    uint32_t bf4[4];
                    ldsm_x4(bf4, smem_u32(&W1s[(kt * 16 + xrow) * 72 + ks * 16 + xk]));
                    mma_f16(d0, afr[ks], bf4, d0);
                    mma_f16(d1, afr[ks], bf4 + 2, d1);
                }
                int col0 = (2 * kt) * 8 + 2 * c4, col1 = (2 * kt + 1) * 8 + 2 * c4;
                float a0 = d0[0] + b1[col0],     a1 = d0[1] + b1[col0 + 1];
                float a2 = d0[2] + b1[col0],     a3 = d0[3] + b1[col0 + 1];
                float a4 = d1[0] + b1[col1],     a5 = d1[1] + b1[col1 + 1];
                float a6 = d1[2] + b1[col1],     a7 = d1[3] + b1[col1 + 1];
                a0 = 0.5f * a0 * (1.f + erff(a0 * 0.70710678118654752f));
                a1 = 0.5f * a1 * (1.f + erff(a1 * 0.70710678118654752f));
                a2 = 0.5f * a2 * (1.f + erff(a2 * 0.70710678118654752f));
                a3 = 0.5f * a3 * (1.f + erff(a3 * 0.70710678118654752f));
                a4 = 0.5f * a4 * (1.f + erff(a4 * 0.70710678118654752f));
                a5 = 0.5f * a5 * (1.f + erff(a5 * 0.70710678118654752f));
                a6 = 0.5f * a6 * (1.f + erff(a6 * 0.70710678118654752f));
                a7 = 0.5f * a7 * (1.f + erff(a7 * 0.70710678118654752f));
                afg[kt][0] = packh2(a0, a1);
                afg[kt][1] = packh2(a2, a3);
                afg[kt][2] = packh2(a4, a5);
                afg[kt][3] = packh2(a6, a7);
            }
        }

        float xf[8][4];
#pragma unroll
        for (int nt = 0; nt < 8; nt++) {
            float a2c[4] = {0.f, 0.f, 0.f, 0.f};
#pragma unroll
            for (int ktp = 0; ktp < 8; ktp++) {
                uint32_t bf4[4];
                ldsm_x4(bf4, smem_u32(&W2s[(nt * 8 + r8) * 264 + ktp * 32 + m4 * 8]));
                mma_f16(a2c, afg[2 * ktp], bf4, a2c);
                mma_f16(a2c, afg[2 * ktp + 1], bf4 + 2, a2c);
            }
            int col = nt * 8 + 2 * c4;
            float bb0 = b2[col], bb1 = b2[col + 1];
#pragma unroll
            for (int half = 0; half < 2; half++) {
                long row = bm + r0 + g4 + 8 * half;
                float v0 = a2c[2 * half] + bb0 + xres[nt][2 * half];
                float v1 = a2c[2 * half + 1] + bb1 + xres[nt][2 * half + 1];
                xf[nt][2 * half] = v0; xf[nt][2 * half + 1] = v1;
                *(float2*)(outx + row * 64 + col) = make_float2(v0, v1);
                if (xhout)
                    *(uint32_t*)(xhout + row * 64 + col) = packh2(v0, v1);
            }
        }
        if (h16out) {
            float s0 = 0.f, s1 = 0.f;
#pragma unroll
            for (int nt = 0; nt < 8; nt++) {
                s0 += xf[nt][0] + xf[nt][1];
                s1 += xf[nt][2] + xf[nt][3];
            }
            s0 += __shfl_xor_sync(0xffffffffu, s0, 1);
            s0 += __shfl_xor_sync(0xffffffffu, s0, 2);
            s1 += __shfl_xor_sync(0xffffffffu, s1, 1);
            s1 += __shfl_xor_sync(0xffffffffu, s1, 2);
            float m0 = s0 * (1.f / 64.f), m1 = s1 * (1.f / 64.f);
            float q0 = 0.f, q1 = 0.f;
#pragma unroll
            for (int nt = 0; nt < 8; nt++) {
                float d0 = xf[nt][0] - m0, d1 = xf[nt][1] - m0;
                float d2 = xf[nt][2] - m1, d3 = xf[nt][3] - m1;
                q0 += d0 * d0 + d1 * d1;
                q1 += d2 * d2 + d3 * d3;
            }
            q0 += __shfl_xor_sync(0xffffffffu, q0, 1);
            q0 += __shfl_xor_sync(0xffffffffu, q0, 2);
            q1 += __shfl_xor_sync(0xffffffffu, q1, 1);
            q1 += __shfl_xor_sync(0xffffffffu, q1, 2);
            float rs0 = rsqrtf(q0 * (1.f / 64.f) + 1e-5f);
            float rs1 = rsqrtf(q1 * (1.f / 64.f) + 1e-5f);
#pragma unroll
            for (int nt = 0; nt < 8; nt++) {
                int col = nt * 8 + 2 * c4;
                float g0 = lng1n[col], g1 = lng1n[col + 1];
                float be0 = lnb1n[col], be1 = lnb1n[col + 1];
                long row0g = bm + r0 + g4;
                *(uint32_t*)(h16out + row0g * 64 + col) =
                    packh2((xf[nt][0] - m0) * rs0 * g0 + be0, (xf[nt][1] - m0) * rs0 * g1 + be1);
                *(uint32_t*)(h16out + (row0g + 8) * 64 + col) =
                    packh2((xf[nt][2] - m1) * rs1 * g0 + be0, (xf[nt][3] - m1) * rs1 * g1 + be1);
            }
        }
        __syncwarp();
    }
}

// ---------------- fused squash + capsule predictions (fp16 out) ----------------
__global__ void caps_usq_k(const float* __restrict__ pc, const float* __restrict__ cw,
                           __half* __restrict__ u) {
    __shared__ float w_s[8 * 48];
    int i = blockIdx.x;
    for (int t = threadIdx.x; t < 384; t += 256) w_s[t] = cw[(long)i * 384 + t];
    __syncthreads();
    int b = threadIdx.x;
    int i32 = i >> 5, y = (i >> 3) & 3, xq = i & 7;
    const float* src = pc + (((long)b * 4 + y) * 8 + xq) * 256 + i32 * 8;
    float ce[8];
    float l2 = 0.f;
#pragma unroll
    for (int e = 0; e < 8; e++) { ce[e] = src[e]; l2 += ce[e] * ce[e]; }
    float sc = sqrtf(l2) / (1.f + l2);
#pragma unroll
    for (int e = 0; e < 8; e++) ce[e] *= sc;
    __half* up = u + ((long)b * 1024 + i) * 48;
#pragma unroll 4
    for (int o = 0; o < 48; o++) {
        float s = 0.f;
#pragma unroll
        for (int e = 0; e < 8; e++) s = fmaf(ce[e], w_s[e * 48 + o], s);
        up[o] = __float2half(s);
    }
}

// ---------------- dynamic routing ----------------
#define ROUT_SMEM ((49152 + 3072 + 96) * 4)
__global__ void __launch_bounds__(256) routing_k(const __half* __restrict__ u,
                                                 const float* __restrict__ br,
                                                 float* __restrict__ out) {
    extern __shared__ float smr[];
    float* us = smr;
    float* bb = smr + 49152;
    float* S  = bb + 3072;
    float* v  = S + 48;
    int b = blockIdx.x, tid = threadIdx.x, lane = tid & 31;
    const __half* ub = u + (long)b * 1024 * 48;
    for (int i = tid; i < 49152; i += 256) us[i] = __half2float(ub[i]);
    for (int i = tid; i < 3072; i += 256) bb[i] = br[i];
    __syncthreads();

    for (int it = 0; it < 4; it++) {
        if (tid < 48) S[tid] = 0.f;
        __syncthreads();
        float acc[48];
#pragma unroll
        for (int o = 0; o < 48; o++) acc[o] = 0.f;
        for (int i = tid; i < 1024; i += 256) {
            float b0 = bb[i * 3], b1 = bb[i * 3 + 1], b2 = bb[i * 3 + 2];
            float m = fmaxf(b0, fmaxf(b1, b2));
            float e0 = expf(b0 - m), e1 = expf(b1 - m), e2 = expf(b2 - m);
            float inv = 1.f / (e0 + e1 + e2);
            float c[3] = {e0 * inv, e1 * inv, e2 * inv};
            const float* up = &us[i * 48];
#pragma unroll
            for (int j = 0; j < 3; j++)
#pragma unroll
                for (int o = 0; o < 16; o++)
                    acc[j * 16 + o] = fmaf(c[j], up[j * 16 + o], acc[j * 16 + o]);
        }
#pragma unroll
        for (int o = 0; o < 48; o++) {
            float s = acc[o];
#pragma unroll
            for (int d = 16; d; d >>= 1) s += __shfl_xor_sync(0xffffffffu, s, d);
            if (lane == 0) atomicAdd(&S[o], s);
        }
        __syncthreads();
        if (tid < 3) {
            float l2 = 0.f;
            for (int o = 0; o < 16; o++) { float t = S[tid * 16 + o]; l2 += t * t; }
            float sc = sqrtf(l2) / (1.f + l2);
            for (int o = 0; o < 16; o++) v[tid * 16 + o] = S[tid * 16 + o] * sc;
            if (it == 3) out[b * 3 + tid] = l2 / (1.f + l2);
        }
        __syncthreads();
        if (it < 3) {
            for (int i = tid; i < 1024; i += 256) {
                const float* up = &us[i * 48];
#pragma unroll
                for (int j = 0; j < 3; j++) {
                    float s = 0.f;
#pragma unroll
                    for (int o = 0; o < 16; o++) s = fmaf(up[j * 16 + o], v[j * 16 + o], s);
                    bb[i * 3 + j] += s;
                }
            }
            __syncthreads();
        }
    }
}

// ---------------- host ----------------
extern "C" void kernel_launch(void* const* d_in, const int* in_sizes, int n_in,
                              void* d_out, int out_size) {
    const float* x_in    = (const float*)d_in[0];
    const float* conv1_w = (const float*)d_in[1];
    const float* conv2_w = (const float*)d_in[2];
    const float* pos_emb = (const float*)d_in[3];
    const float* ln1_g   = (const float*)d_in[4];
    const float* ln1_b   = (const float*)d_in[5];
    const float* qkv_w   = (const float*)d_in[6];
    const float* out_w   = (const float*)d_in[7];
    const float* out_b   = (const float*)d_in[8];
    const float* ln2_g   = (const float*)d_in[9];
    const float* ln2_b   = (const float*)d_in[10];
    const float* ff1_w   = (const float*)d_in[11];
    const float* ff1_b   = (const float*)d_in[12];
    const float* ff2_w   = (const float*)d_in[13];
    const float* ff2_b   = (const float*)d_in[14];
    const float* pcaps_w = (const float*)d_in[15];
    const float* pcaps_b = (const float*)d_in[16];
    const float* caps_w  = (const float*)d_in[17];
    const float* b_route = (const float*)d_in[18];
    float* out = (float*)d_out;

    float *xb, *pc;
    __half *col1h, *y1h, *p1h, *y2h, *xh, *h16g, *aoh, *uh, *qh, *owh, *w1h, *w2h, *cw1h, *cw2h, *cw3h;
    cudaGetSymbolAddress((void**)&col1h, g_col1h);
    cudaGetSymbolAddress((void**)&y1h,  g_y1h);
    cudaGetSymbolAddress((void**)&p1h,  g_p1h);
    cudaGetSymbolAddress((void**)&y2h,  g_y2h);
    cudaGetSymbolAddress((void**)&xb,   g_x);
    cudaGetSymbolAddress((void**)&xh,   g_xh);
    cudaGetSymbolAddress((void**)&h16g, g_h16);
    cudaGetSymbolAddress((void**)&aoh,  g_aoh);
    cudaGetSymbolAddress((void**)&pc,   g_pc);
    cudaGetSymbolAddress((void**)&uh,   g_uh);
    cudaGetSymbolAddress((void**)&qh,   g_qh);
    cudaGetSymbolAddress((void**)&owh,  g_owh);
    cudaGetSymbolAddress((void**)&w1h,  g_w1h);
    cudaGetSymbolAddress((void**)&w2h,  g_w2h);
    cudaGetSymbolAddress((void**)&cw1h, g_cw1h);
    cudaGetSymbolAddress((void**)&cw2h, g_cw2h);
    cudaGetSymbolAddress((void**)&cw3h, g_cw3h);

    cudaFuncSetAttribute(attn_fused_k, cudaFuncAttributeMaxDynamicSharedMemorySize, ATTNH_SMEM);
    cudaFuncSetAttribute(tail_fused_k, cudaFuncAttributeMaxDynamicSharedMemorySize, TAIL_SMEM);
    cudaFuncSetAttribute(hconv1_k,     cudaFuncAttributeMaxDynamicSharedMemorySize, HC1_SMEM);
    cudaFuncSetAttribute(hconv2_k,     cudaFuncAttributeMaxDynamicSharedMemorySize, HC2_SMEM);
    cudaFuncSetAttribute(hconv3_k,     cudaFuncAttributeMaxDynamicSharedMemorySize, HC3_SMEM);
    cudaFuncSetAttribute(routing_k,    cudaFuncAttributeMaxDynamicSharedMemorySize, ROUT_SMEM);

    prep_qkv_k<<<CDIV(12 * 12 * 3 * 4096, 256), 256>>>(qkv_w, qh);
    prep_ow_k <<<CDIV(12 * 64 * 768, 256), 256>>>(out_w, owh);
    prep_w1_k <<<CDIV(12 * 256 * 64, 256), 256>>>(ff1_w, w1h);
    prep_w2_k <<<CDIV(12 * 64 * 256, 256), 256>>>(ff2_w, w2h);
    prep_cw1_k<<<CDIV(64 * 32, 256), 256>>>(conv1_w, cw1h);
    prep_cwhwc_k<<<CDIV(64 * 576, 256), 256>>>(conv2_w, cw2h, 64);
    prep_cwhwc_k<<<CDIV(256 * 576, 256), 256>>>(pcaps_w, cw3h, 256);

    im2col1h_k<<<(int)CDIV((long)737280 * 32, 256), 256>>>(x_in, col1h);
    hconv1_k<<<737280 / 128, 256, HC1_SMEM>>>(col1h, cw1h, y1h);
    maxpool_k<__half, __half><<<(int)CDIV((long)256 * 20 * 36 * 64, 256), 256>>>(
        y1h, p1h, 256, 40, 72, 64, 20, 36, nullptr);
    hconv2_k<<<184320 / 128, 256, HC2_SMEM>>>(p1h, cw2h, y2h);
    maxpool_k<__half, float><<<(int)CDIV((long)256 * 10 * 18 * 64, 256), 256>>>(
        y2h, xb, 256, 20, 36, 64, 10, 18, pos_emb);

    const int M = 46080;
    ln1h_k<<<M / 8, 256>>>(xb, ln1_g, ln1_b, h16g, M);
    for (int pass = 0; pass < 2; pass++) {
        for (int l = 0; l < 12; l++) {
            bool last = (pass == 1) && (l == 11);
            int ln = (l + 1) % 12;
            attn_fused_k<<<256 * 12, 384, ATTNH_SMEM>>>(h16g, qh + (long)l * 147456, aoh);
            tail_fused_k<<<120, 256, TAIL_SMEM>>>(aoh, owh + (long)l * 49152, out_b + l * 64,
                                                  xb, w1h + (long)l * 16384, ff1_b + l * 256,
                                                  w2h + (long)l * 16384, ff2_b + l * 64,
                                                  ln2_g + l * 64, ln2_b + l * 64, xb,
                                                  last ? nullptr : ln1_g + ln * 64,
                                                  last ? nullptr : ln1_b + ln * 64,
                                                  last ? nullptr : h16g,
                                                  last ? xh : nullptr);
        }
    }

    // ---- PrimaryCaps + routing (fp16 fused-im2col conv, fused squash) ----
    hconv3_k<<<dim3(2, 64), 256, HC3_SMEM>>>(xh, cw3h, pcaps_b, pc);
    caps_usq_k<<<1024, 256>>>(pc, caps_w, uh);
    routing_k<<<256, 256, ROUT_SMEM>>>(uh, b_route, out);
}

// round 16
// speedup vs baseline: 1.0248x; 1.0248x over previous
#include <cuda_runtime.h>
#include <cuda_fp16.h>
#include <math.h>
#include <stdint.h>

#define CDIV(a,b) (((a)+(b)-1)/(b))

// ---------------- static scratch (no allocations allowed) ----------------
__device__ __half g_col1h[737280 * 32];
__device__ __half g_y1h [737280 * 64];
__device__ __half g_p1h [184320 * 64];
__device__ __half g_y2h [184320 * 64];
__device__ float  g_x   [46080 * 64];
__device__ __half g_h16 [46080 * 64];
__device__ __half g_aoh [46080 * 768];
__device__ float  g_col3[8192 * 576];
__device__ float  g_wtp [576 * 256];
__device__ float  g_pc  [8192 * 256];
__device__ float  g_caps[256 * 1024 * 8];
__device__ __half g_uh  [256 * 1024 * 48];
__device__ __half g_qh  [12 * 12 * 3 * 64 * 64];
__device__ __half g_owh [12 * 64 * 768];
__device__ __half g_w1h [12 * 256 * 64];
__device__ __half g_w2h [12 * 64 * 256];
__device__ __half g_cw1h[64 * 32];
__device__ __half g_cw2h[64 * 576];

// ---------------- weight prep ----------------
__global__ void prep_qkv_k(const float* __restrict__ qw, __half* __restrict__ qh) {
    int idx = blockIdx.x * 256 + threadIdx.x;
    if (idx >= 12 * 12 * 3 * 4096) return;
    int k = idx & 63, n = (idx >> 6) & 63;
    int rest = idx >> 12;
    int mat = rest % 3; rest /= 3;
    int h = rest % 12, l = rest / 12;
    int moff = (mat == 0) ? 768 : (mat == 1) ? 1536 : 0;
    qh[idx] = __float2half(qw[(long)l * 64 * 2304 + (long)k * 2304 + moff + h * 64 + n]);
}
__global__ void prep_ow_k(const float* __restrict__ ow, __half* __restrict__ oh) {
    int idx = blockIdx.x * 256 + threadIdx.x;
    if (idx >= 12 * 64 * 768) return;
    int k = idx % 768, n = (idx / 768) % 64, l = idx / 49152;
    oh[idx] = __float2half(ow[(long)l * 49152 + (long)k * 64 + n]);
}
__global__ void prep_w1_k(const float* __restrict__ w1, __half* __restrict__ o) {
    int idx = blockIdx.x * 256 + threadIdx.x;
    if (idx >= 12 * 256 * 64) return;
    int k = idx & 63, n = (idx >> 6) & 255, l = idx >> 14;
    o[idx] = __float2half(w1[(long)l * 16384 + (long)k * 256 + n]);
}
__global__ void prep_w2_k(const float* __restrict__ w2, __half* __restrict__ o) {
    int idx = blockIdx.x * 256 + threadIdx.x;
    if (idx >= 12 * 64 * 256) return;
    int k = idx & 255, n = (idx >> 8) & 63, l = idx >> 14;
    o[idx] = __float2half(w2[(long)l * 16384 + (long)k * 64 + n]);
}
__global__ void prep_cw1_k(const float* __restrict__ w, __half* __restrict__ o) {
    int idx = blockIdx.x * 256 + threadIdx.x;
    if (idx >= 64 * 32) return;
    int k = idx & 31, n = idx >> 5;
    o[idx] = __float2half(k < 27 ? w[n * 27 + k] : 0.f);
}
__global__ void prep_cw2_k(const float* __restrict__ w, __half* __restrict__ o) {
    int idx = blockIdx.x * 256 + threadIdx.x;
    if (idx >= 64 * 576) return;
    int kk = idx % 576, n = idx / 576;
    int ci = kk & 63, tap = kk >> 6;
    o[idx] = __float2half(w[n * 576 + ci * 9 + tap]);
}

// ---------------- im2col (conv1): one thread per row, vectorized stores ----------------
__global__ void im2col1v_k(const float* __restrict__ x, __half* __restrict__ col) {
    int m = blockIdx.x * 256 + threadIdx.x;
    if (m >= 737280) return;
    int ow = m % 72;
    int t  = m / 72;
    int oh = t % 40;
    int b  = t / 40;
    __half buf[32];
#pragma unroll
    for (int ci = 0; ci < 3; ci++)
#pragma unroll
        for (int kh = 0; kh < 3; kh++)
#pragma unroll
            for (int kw = 0; kw < 3; kw++) {
                int ih = oh + kh - 1, iw = ow + kw - 1;
                float v = 0.f;
                if ((unsigned)ih < 40u && (unsigned)iw < 72u)
                    v = x[(((long)b * 3 + ci) * 40 + ih) * 72 + iw];
                buf[ci * 9 + kh * 3 + kw] = __float2half(v);
            }
#pragma unroll
    for (int k = 27; k < 32; k++) buf[k] = __float2half(0.f);
    uint4* dst = (uint4*)(col + (long)m * 32);
    const uint4* s = (const uint4*)buf;
    dst[0] = s[0]; dst[1] = s[1]; dst[2] = s[2]; dst[3] = s[3];
}

__global__ void im2col3_k(const float* __restrict__ tk, float* __restrict__ col) {
    long idx = (long)blockIdx.x * blockDim.x + threadIdx.x;
    const long total = (long)8192 * 576;
    if (idx >= total) return;
    int kk = (int)(idx % 576);
    long m = idx / 576;
    int ow = (int)(m % 8);
    int t  = (int)(m / 8);
    int oh = t % 4;
    int b  = t / 4;
    int ci = kk % 64;
    int kw = (kk / 64) % 3;
    int kh = kk / 192;
    int ih = oh * 2 + kh, iw = ow * 2 + kw;
    col[idx] = tk[((long)b * 180 + ih * 18 + iw) * 64 + ci];
}

__global__ void wtrans_hwc(const float* __restrict__ w, float* __restrict__ wt, int O, int CI) {
    int K = CI * 9;
    int i = blockIdx.x * blockDim.x + threadIdx.x;
    if (i >= O * K) return;
    int o = i / K, r = i % K;
    int ci = r / 9, kh = (r % 9) / 3, kw = r % 3;
    wt[((kh * 3 + kw) * CI + ci) * O + o] = w[i];
}

// ---------------- tf32 helpers ----------------
__device__ __forceinline__ float f2tf(float f) {
    uint32_t r;
    asm("cvt.rna.tf32.f32 %0, %1;" : "=r"(r) : "f"(f));
    return __uint_as_float(r);
}
__device__ __forceinline__ void mma_tf32(float d[4], const uint32_t a[4], const uint32_t b[2],
                                         const float c[4]) {
    asm("mma.sync.aligned.m16n8k8.row.col.f32.tf32.tf32.f32 "
        "{%0,%1,%2,%3},{%4,%5,%6,%7},{%8,%9},{%10,%11,%12,%13};"
        : "=f"(d[0]), "=f"(d[1]), "=f"(d[2]), "=f"(d[3])
        : "r"(a[0]), "r"(a[1]), "r"(a[2]), "r"(a[3]), "r"(b[0]), "r"(b[1]),
          "f"(c[0]), "f"(c[1]), "f"(c[2]), "f"(c[3]));
}

// ---------------- fp16 mma helpers ----------------
__device__ __forceinline__ uint32_t smem_u32(const void* p) {
    return (uint32_t)__cvta_generic_to_shared(p);
}
__device__ __forceinline__ void ldsm_x4(uint32_t r[4], uint32_t addr) {
    asm volatile("ldmatrix.sync.aligned.m8n8.x4.shared.b16 {%0,%1,%2,%3}, [%4];"
        : "=r"(r[0]), "=r"(r[1]), "=r"(r[2]), "=r"(r[3]) : "r"(addr));
}
__device__ __forceinline__ void ldsm_x2(uint32_t r[2], uint32_t addr) {
    asm volatile("ldmatrix.sync.aligned.m8n8.x2.shared.b16 {%0,%1}, [%2];"
        : "=r"(r[0]), "=r"(r[1]) : "r"(addr));
}
__device__ __forceinline__ void ldsm_x4t(uint32_t r[4], uint32_t addr) {
    asm volatile("ldmatrix.sync.aligned.m8n8.x4.trans.shared.b16 {%0,%1,%2,%3}, [%4];"
        : "=r"(r[0]), "=r"(r[1]), "=r"(r[2]), "=r"(r[3]) : "r"(addr));
}
__device__ __forceinline__ void mma_f16(float d[4], const uint32_t a[4], const uint32_t b[2],
                                        const float c[4]) {
    asm volatile("mma.sync.aligned.m16n8k16.row.col.f32.f16.f16.f32 "
        "{%0,%1,%2,%3},{%4,%5,%6,%7},{%8,%9},{%10,%11,%12,%13};"
        : "=f"(d[0]), "=f"(d[1]), "=f"(d[2]), "=f"(d[3])
        : "r"(a[0]), "r"(a[1]), "r"(a[2]), "r"(a[3]), "r"(b[0]), "r"(b[1]),
          "f"(c[0]), "f"(c[1]), "f"(c[2]), "f"(c[3]));
}
__device__ __forceinline__ uint32_t packh2(float a, float b) {
    __half2 h = __floats2half2_rn(a, b);
    return *(uint32_t*)&h;
}

// ---------------- tf32 tensor-core GEMM (pcaps) ----------------
template <int EPI>
__global__ void __launch_bounds__(256) tgemm_k(const float* __restrict__ A, const float* __restrict__ Bm,
                                               const float* __restrict__ bias,
                                               float* __restrict__ C, int M, int N, int K) {
    __shared__ float As[128 * 36];
    __shared__ float Bs[32 * 68];
    const int bm = blockIdx.y * 128, bn = blockIdx.x * 64;
    const int tid = threadIdx.x, lane = tid & 31, w = tid >> 5;
    const int g4 = lane >> 2, c4 = lane & 3;
    const int wm = (w & 3) * 32, wn = (w >> 2) * 32;

    float acc[2][4][4];
#pragma unroll
    for (int mt = 0; mt < 2; mt++)
#pragma unroll
        for (int nt = 0; nt < 4; nt++)
#pragma unroll
            for (int i = 0; i < 4; i++) acc[mt][nt][i] = 0.f;

    const int ar = tid >> 1, akb = (tid & 1) * 16;
    const int bk = tid >> 3, bn0 = (tid & 7) * 8;
    const float* Arow = A + (long)(bm + ar) * K;

    for (int k0 = 0; k0 < K; k0 += 32) {
        float4 av[4], bv[2];
#pragma unroll
        for (int i = 0; i < 4; i++) {
            int gk = k0 + akb + 4 * i;
            av[i] = (gk + 4 <= K) ? *(const float4*)(Arow + gk) : make_float4(0.f, 0.f, 0.f, 0.f);
        }
        {
            int gk = k0 + bk;
            if (gk < K) {
                bv[0] = *(const float4*)(Bm + (long)gk * N + bn + bn0);
                bv[1] = *(const float4*)(Bm + (long)gk * N + bn + bn0 + 4);
            } else {
                bv[0] = make_float4(0.f, 0.f, 0.f, 0.f);
                bv[1] = bv[0];
            }
        }
        __syncthreads();
#pragma unroll
        for (int i = 0; i < 4; i++) {
            float* p = &As[ar * 36 + akb + 4 * i];
            p[0] = f2tf(av[i].x); p[1] = f2tf(av[i].y); p[2] = f2tf(av[i].z); p[3] = f2tf(av[i].w);
        }
        {
            float* p = &Bs[bk * 68 + bn0];
            p[0] = f2tf(bv[0].x); p[1] = f2tf(bv[0].y); p[2] = f2tf(bv[0].z); p[3] = f2tf(bv[0].w);
            p[4] = f2tf(bv[1].x); p[5] = f2tf(bv[1].y); p[6] = f2tf(bv[1].z); p[7] = f2tf(bv[1].w);
        }
        __syncthreads();
#pragma unroll
        for (int ks = 0; ks < 4; ks++) {
            uint32_t bfr[4][2], afr[2][4];
#pragma unroll
            for (int nt = 0; nt < 4; nt++) {
                int col = wn + nt * 8 + g4;
                bfr[nt][0] = __float_as_uint(Bs[(ks * 8 + c4) * 68 + col]);
                bfr[nt][1] = __float_as_uint(Bs[(ks * 8 + c4 + 4) * 68 + col]);
            }
#pragma unroll
            for (int mt = 0; mt < 2; mt++) {
                int base = (wm + mt * 16 + g4) * 36 + ks * 8 + c4;
                afr[mt][0] = __float_as_uint(As[base]);
                afr[mt][1] = __float_as_uint(As[base + 8 * 36]);
                afr[mt][2] = __float_as_uint(As[base + 4]);
                afr[mt][3] = __float_as_uint(As[base + 8 * 36 + 4]);
            }
#pragma unroll
            for (int mt = 0; mt < 2; mt++)
#pragma unroll
                for (int nt = 0; nt < 4; nt++)
                    mma_tf32(acc[mt][nt], afr[mt], bfr[nt], acc[mt][nt]);
        }
        __syncthreads();
    }

#pragma unroll
    for (int nt = 0; nt < 4; nt++) {
        int col = bn + wn + nt * 8 + 2 * c4;
        float b0 = 0.f, b1 = 0.f;
        if (EPI >= 2) { b0 = bias[col]; b1 = bias[col + 1]; }
#pragma unroll
        for (int mt = 0; mt < 2; mt++) {
#pragma unroll
            for (int half = 0; half < 2; half++) {
                long row = bm + wm + mt * 16 + g4 + 8 * half;
                float v0 = acc[mt][nt][2 * half], v1 = acc[mt][nt][2 * half + 1];
                if (EPI == 1) { v0 = fmaxf(v0, 0.f); v1 = fmaxf(v1, 0.f); }
                if (EPI >= 2) { v0 += b0; v1 += b1; }
                *(float2*)(C + row * N + col) = make_float2(v0, v1);
            }
        }
    }
}

// ---------------- conv1 fp16 GEMM ----------------
#define HC1_SMEM ((64 * 40 + 128 * 40) * 2)
__global__ void __launch_bounds__(256) hconv1_k(const __half* __restrict__ col,
                                                const __half* __restrict__ wch,
                                                __half* __restrict__ y1) {
    extern __shared__ __half sm1[];
    __half* Ws = sm1;
    __half* As = sm1 + 64 * 40;

    const int bm = blockIdx.x * 128;
    const int tid = threadIdx.x, lane = tid & 31, w = tid >> 5;
    const int g4 = lane >> 2, c4 = lane & 3;
    const int lmrow = lane & 15, lmk = (lane >> 4) * 8;
    const int b2row = lane & 7, b2k = ((lane >> 3) & 1) * 8;
    const int r0 = w * 16;

    for (int idx = tid; idx < 64 * 4; idx += 256) {
        int n = idx >> 2, q = idx & 3;
        *(uint4*)&Ws[n * 40 + q * 8] = *(const uint4*)(wch + n * 32 + q * 8);
    }
    __syncthreads();

    const int ar = tid >> 1, apart = (tid & 1) * 16;
    {
        const uint4* src = (const uint4*)(col + (long)(bm + ar) * 32 + apart);
        uint4* dst = (uint4*)&As[ar * 40 + apart];
        dst[0] = src[0]; dst[1] = src[1];
    }
    __syncwarp();

    uint32_t afr[2][4];
#pragma unroll
    for (int ks = 0; ks < 2; ks++)
        ldsm_x4(afr[ks], smem_u32(&As[(r0 + lmrow) * 40 + ks * 16 + lmk]));

#pragma unroll
    for (int nt = 0; nt < 8; nt++) {
        float acc[4] = {0.f, 0.f, 0.f, 0.f};
#pragma unroll
        for (int ks = 0; ks < 2; ks++) {
            uint32_t bf[2];
            ldsm_x2(bf, smem_u32(&Ws[(nt * 8 + b2row) * 40 + ks * 16 + b2k]));
            mma_f16(acc, afr[ks], bf, acc);
        }
        int coln = nt * 8 + 2 * c4;
#pragma unroll
        for (int half = 0; half < 2; half++) {
            long row = bm + r0 + g4 + 8 * half;
            *(uint32_t*)(y1 + row * 64 + coln) =
                packh2(fmaxf(acc[2 * half], 0.f), fmaxf(acc[2 * half + 1], 0.f));
        }
    }
}

// ---------------- conv2 direct (fused im2col) ----------------
#define HC2_SMEM (64 * 584 * 2 + 128 * 72 * 2)
__global__ void __launch_bounds__(256) hconv2_k(const __half* __restrict__ p1,
                                                const __half* __restrict__ wch,
                                                __half* __restrict__ y2) {
    extern __shared__ __half smc[];
    __half* Ws = smc;
    __half* As = smc + 64 * 584;

    const int bm = blockIdx.x * 128;
    const int tid = threadIdx.x, lane = tid & 31, w = tid >> 5;
    const int g4 = lane >> 2, c4 = lane & 3;
    const int lmrow = lane & 15, lmk = (lane >> 4) * 8;
    const int m4 = lane >> 3, r8 = lane & 7;
    const int xrow = ((m4 >> 1) << 3) + r8, xk = (m4 & 1) * 8;
    const int r0 = w * 16;

    for (int idx = tid; idx < 64 * 72; idx += 256) {
        int n = idx / 72, q = idx % 72;
        *(uint4*)&Ws[n * 584 + q * 8] = *(const uint4*)(wch + n * 576 + q * 8);
    }
    __syncthreads();

    float acc[8][4];
#pragma unroll
    for (int nt = 0; nt < 8; nt++)
#pragma unroll
        for (int i = 0; i < 4; i++) acc[nt][i] = 0.f;

    const int ar = tid >> 1, apart = (tid & 1) * 32;
    const int m = bm + ar;
    const int bidx = m / 720, rem = m % 720;
    const int oh = rem / 36, owp = rem % 36;

#pragma unroll
    for (int kc = 0; kc < 9; kc++) {
        int kh = kc / 3, kw = kc % 3;
        int ih = oh + kh - 1, iw = owp + kw - 1;
        uint4 v[4];
        if ((unsigned)ih < 20u && (unsigned)iw < 36u) {
            const uint4* src = (const uint4*)(p1 + (((long)(bidx * 20 + ih)) * 36 + iw) * 64 + apart);
            v[0] = src[0]; v[1] = src[1]; v[2] = src[2]; v[3] = src[3];
        } else {
            v[0] = make_uint4(0, 0, 0, 0); v[1] = v[0]; v[2] = v[0]; v[3] = v[0];
        }
        uint4* dst = (uint4*)&As[ar * 72 + apart];
        dst[0] = v[0]; dst[1] = v[1]; dst[2] = v[2]; dst[3] = v[3];
        __syncwarp();
        uint32_t afr[4][4];
#pragma unroll
        for (int ks = 0; ks < 4; ks++)
            ldsm_x4(afr[ks], smem_u32(&As[(r0 + lmrow) * 72 + ks * 16 + lmk]));
#pragma unroll
        for (int ntp = 0; ntp < 4; ntp++) {
#pragma unroll
            for (int ks = 0; ks < 4; ks++) {
                uint32_t bf4[4];
                ldsm_x4(bf4, smem_u32(&Ws[(ntp * 16 + xrow) * 584 + kc * 64 + ks * 16 + xk]));
                mma_f16(acc[2 * ntp], afr[ks], bf4, acc[2 * ntp]);
                mma_f16(acc[2 * ntp + 1], afr[ks], bf4 + 2, acc[2 * ntp + 1]);
            }
        }
        __syncwarp();
    }

#pragma unroll
    for (int nt = 0; nt < 8; nt++) {
        int col = nt * 8 + 2 * c4;
#pragma unroll
        for (int half = 0; half < 2; half++) {
            long row = bm + r0 + g4 + 8 * half;
            *(uint32_t*)(y2 + row * 64 + col) =
                packh2(fmaxf(acc[nt][2 * half], 0.f), fmaxf(acc[nt][2 * half + 1], 0.f));
        }
    }
}

// ---------------- maxpool fp16->fp16, 2 channels per thread ----------------
__global__ void maxpool_h2_k(const __half2* __restrict__ in, __half2* __restrict__ out,
                             int Bn, int IH, int IW, int OH, int OW) {
    long idx = (long)blockIdx.x * blockDim.x + threadIdx.x;
    long total = (long)Bn * OH * OW * 32;
    if (idx >= total) return;
    int c2 = (int)(idx & 31);
    long r = idx >> 5;
    int ow = (int)(r % OW); r /= OW;
    int oh = (int)(r % OH);
    int b  = (int)(r / OH);
    __half2 m = __floats2half2_rn(-65504.f, -65504.f);
#pragma unroll
    for (int kh = 0; kh < 3; kh++) {
        int ih = oh * 2 - 1 + kh;
        if (ih < 0 || ih >= IH) continue;
#pragma unroll
        for (int kw = 0; kw < 3; kw++) {
            int iw = ow * 2 - 1 + kw;
            if (iw < 0 || iw >= IW) continue;
            m = __hmax2(m, in[(((long)b * IH + ih) * IW + iw) * 32 + c2]);
        }
    }
    out[idx] = m;
}

// ---------------- maxpool fp16->fp32 + pos-emb, 2 channels per thread ----------------
__global__ void maxpool_h2f_k(const __half2* __restrict__ in, float* __restrict__ out,
                              int Bn, int IH, int IW, int OH, int OW,
                              const float* __restrict__ pos) {
    long idx = (long)blockIdx.x * blockDim.x + threadIdx.x;
    long total = (long)Bn * OH * OW * 32;
    if (idx >= total) return;
    int c2 = (int)(idx & 31);
    long r = idx >> 5;
    int ow = (int)(r % OW); r /= OW;
    int oh = (int)(r % OH);
    int b  = (int)(r / OH);
    float m0 = -1e30f, m1 = -1e30f;
#pragma unroll
    for (int kh = 0; kh < 3; kh++) {
        int ih = oh * 2 - 1 + kh;
        if (ih < 0 || ih >= IH) continue;
#pragma unroll
        for (int kw = 0; kw < 3; kw++) {
            int iw = ow * 2 - 1 + kw;
            if (iw < 0 || iw >= IW) continue;
            __half2 v = in[(((long)b * IH + ih) * IW + iw) * 32 + c2];
            m0 = fmaxf(m0, __low2float(v));
            m1 = fmaxf(m1, __high2float(v));
        }
    }
    float2 p = *(const float2*)(pos + (oh * OW + ow) * 64 + 2 * c2);
    long obase = (((long)b * OH + oh) * OW + ow) * 64 + 2 * c2;
    *(float2*)(out + obase) = make_float2(m0 + p.x, m1 + p.y);
}

// ---------------- LN1 -> fp16 (layer 0 only) ----------------
__global__ void ln1h_k(const float* __restrict__ x, const float* __restrict__ g,
                       const float* __restrict__ bta, __half* __restrict__ o, int ntok) {
    int warp = (blockIdx.x * blockDim.x + threadIdx.x) >> 5;
    int lane = threadIdx.x & 31;
    if (warp >= ntok) return;
    float v0 = x[(long)warp * 64 + lane];
    float v1 = x[(long)warp * 64 + 32 + lane];
    float s = v0 + v1;
#pragma unroll
    for (int off = 16; off; off >>= 1) s += __shfl_xor_sync(0xffffffffu, s, off);
    float mean = s * (1.f / 64.f);
    float d0 = v0 - mean, d1 = v1 - mean;
    float q = d0 * d0 + d1 * d1;
#pragma unroll
    for (int off = 16; off; off >>= 1) q += __shfl_xor_sync(0xffffffffu, q, off);
    float rstd = rsqrtf(q * (1.f / 64.f) + 1e-5f);
    o[(long)warp * 64 + lane]      = __float2half(d0 * rstd * g[lane] + bta[lane]);
    o[(long)warp * 64 + 32 + lane] = __float2half(d1 * rstd * g[lane + 32] + bta[lane + 32]);
}

// ---------------- fully-fused attention (x4 ldsm) ----------------
#define ATTNH_SMEM ((3 * 192 * 72 + 3 * 64 * 72) * 2)

__global__ void __launch_bounds__(384, 1) attn_fused_k(const __half* __restrict__ h16g,
                                                       const __half* __restrict__ qh,
                                                       __half* __restrict__ out) {
    extern __shared__ __half smh[];
    __half* H16 = smh;
    __half* K16 = smh + 192 * 72;
    __half* V16 = smh + 2 * 192 * 72;
    __half* W16 = smh + 3 * 192 * 72;

    int b = blockIdx.x / 12, h = blockIdx.x % 12;
    int tid = threadIdx.x, lane = tid & 31, w = tid >> 5;
    int g4 = lane >> 2, c4 = lane & 3;
    int lmrow = lane & 15, lmk = (lane >> 4) * 8;
    int m4 = lane >> 3, r8 = lane & 7;
    int xrow = ((m4 >> 1) << 3) + r8, xk = (m4 & 1) * 8;
    int trow = m4 * 8 + r8;
    const int r0 = w * 16;

    {
        const __half* qsrc = qh + (long)h * 12288;
        for (int idx = tid; idx < 192 * 8; idx += 384) {
            int row = idx >> 3, q = idx & 7;
            *(uint4*)&W16[row * 72 + q * 8] = *(const uint4*)(qsrc + row * 64 + q * 8);
        }
    }
    {
        const __half* hb = h16g + (long)b * 180 * 64;
        for (int idx = tid; idx < 180 * 8; idx += 384) {
            int row = idx >> 3, q = idx & 7;
            *(uint4*)&H16[row * 72 + q * 8] = *(const uint4*)(hb + row * 64 + q * 8);
        }
        for (int i = tid; i < 12 * 72; i += 384) H16[180 * 72 + i] = __float2half(0.f);
    }
    __syncthreads();

    uint32_t afr[4][4];
#pragma unroll
    for (int ks = 0; ks < 4; ks++)
        ldsm_x4(afr[ks], smem_u32(&H16[(r0 + lmrow) * 72 + ks * 16 + lmk]));

#pragma unroll
    for (int mat = 0; mat < 2; mat++) {
        const __half* Wm = W16 + mat * 64 * 72;
        __half* dst = mat ? V16 : K16;
#pragma unroll
        for (int ntp = 0; ntp < 4; ntp++) {
            float a0[4] = {0.f, 0.f, 0.f, 0.f}, a1[4] = {0.f, 0.f, 0.f, 0.f};
#pragma unroll
            for (int ks = 0; ks < 4; ks++) {
                uint32_t bf4[4];
                ldsm_x4(bf4, smem_u32(&Wm[(ntp * 16 + xrow) * 72 + ks * 16 + xk]));
                mma_f16(a0, afr[ks], bf4, a0);
                mma_f16(a1, afr[ks], bf4 + 2, a1);
            }
            int col0 = (2 * ntp) * 8 + 2 * c4, col1 = col0 + 8;
            *(uint32_t*)&dst[(r0 + g4) * 72 + col0]     = packh2(a0[0], a0[1]);
            *(uint32_t*)&dst[(r0 + g4 + 8) * 72 + col0] = packh2(a0[2], a0[3]);
            *(uint32_t*)&dst[(r0 + g4) * 72 + col1]     = packh2(a1[0], a1[1]);
            *(uint32_t*)&dst[(r0 + g4 + 8) * 72 + col1] = packh2(a1[2], a1[3]);
        }
    }

    uint32_t afq[4][4];
    {
        const __half* Wm = W16 + 2 * 64 * 72;
        float qacc[8][4];
#pragma unroll
        for (int ntp = 0; ntp < 4; ntp++) {
#pragma unroll
            for (int i = 0; i < 4; i++) { qacc[2 * ntp][i] = 0.f; qacc[2 * ntp + 1][i] = 0.f; }
#pragma unroll
            for (int ks = 0; ks < 4; ks++) {
                uint32_t bf4[4];
                ldsm_x4(bf4, smem_u32(&Wm[(ntp * 16 + xrow) * 72 + ks * 16 + xk]));
                mma_f16(qacc[2 * ntp], afr[ks], bf4, qacc[2 * ntp]);
                mma_f16(qacc[2 * ntp + 1], afr[ks], bf4 + 2, qacc[2 * ntp + 1]);
            }
        }
#pragma unroll
        for (int kt = 0; kt < 4; kt++) {
            afq[kt][0] = packh2(qacc[2 * kt][0],     qacc[2 * kt][1]);
            afq[kt][1] = packh2(qacc[2 * kt][2],     qacc[2 * kt][3]);
            afq[kt][2] = packh2(qacc[2 * kt + 1][0], qacc[2 * kt + 1][1]);
            afq[kt][3] = packh2(qacc[2 * kt + 1][2], qacc[2 * kt + 1][3]);
        }
    }
    __syncthreads();

    float S[24][4];
#pragma unroll
    for (int ntp = 0; ntp < 12; ntp++) {
        float a0[4] = {0.f, 0.f, 0.f, 0.f}, a1[4] = {0.f, 0.f, 0.f, 0.f};
#pragma unroll
        for (int ks = 0; ks < 4; ks++) {
            uint32_t bf4[4];
            ldsm_x4(bf4, smem_u32(&K16[(ntp * 16 + xrow) * 72 + ks * 16 + xk]));
            mma_f16(a0, afq[ks], bf4, a0);
            mma_f16(a1, afq[ks], bf4 + 2, a1);
        }
#pragma unroll
        for (int i = 0; i < 4; i++) {
            S[2 * ntp][i]     = a0[i] * 0.125f;
            S[2 * ntp + 1][i] = a1[i] * 0.125f;
        }
    }

    {
        float mx0 = -1e30f, mx1 = -1e30f;
#pragma unroll
        for (int nt = 0; nt < 24; nt++) {
#pragma unroll
            for (int j = 0; j < 2; j++) {
                int col = nt * 8 + 2 * c4 + j;
                if (col < 180) {
                    mx0 = fmaxf(mx0, S[nt][j]);
                    mx1 = fmaxf(mx1, S[nt][2 + j]);
                }
            }
        }
        mx0 = fmaxf(mx0, __shfl_xor_sync(0xffffffffu, mx0, 1));
        mx0 = fmaxf(mx0, __shfl_xor_sync(0xffffffffu, mx0, 2));
        mx1 = fmaxf(mx1, __shfl_xor_sync(0xffffffffu, mx1, 1));
        mx1 = fmaxf(mx1, __shfl_xor_sync(0xffffffffu, mx1, 2));
        float sum0 = 0.f, sum1 = 0.f;
#pragma unroll
        for (int nt = 0; nt < 24; nt++) {
#pragma unroll
            for (int j = 0; j < 2; j++) {
                int col = nt * 8 + 2 * c4 + j;
                float e0 = (col < 180) ? __expf(S[nt][j] - mx0) : 0.f;
                float e1 = (col < 180) ? __expf(S[nt][2 + j] - mx1) : 0.f;
                S[nt][j] = e0; S[nt][2 + j] = e1;
                sum0 += e0; sum1 += e1;
            }
        }
        sum0 += __shfl_xor_sync(0xffffffffu, sum0, 1);
        sum0 += __shfl_xor_sync(0xffffffffu, sum0, 2);
        sum1 += __shfl_xor_sync(0xffffffffu, sum1, 1);
        sum1 += __shfl_xor_sync(0xffffffffu, sum1, 2);
        float inv0 = 1.f / sum0, inv1 = 1.f / sum1;
#pragma unroll
        for (int nt = 0; nt < 24; nt++) {
            S[nt][0] *= inv0; S[nt][1] *= inv0;
            S[nt][2] *= inv1; S[nt][3] *= inv1;
        }
    }

    uint32_t P[12][4];
#pragma unroll
    for (int kt = 0; kt < 12; kt++) {
        P[kt][0] = packh2(S[2 * kt][0],     S[2 * kt][1]);
        P[kt][1] = packh2(S[2 * kt][2],     S[2 * kt][3]);
        P[kt][2] = packh2(S[2 * kt + 1][0], S[2 * kt + 1][1]);
        P[kt][3] = packh2(S[2 * kt + 1][2], S[2 * kt + 1][3]);
    }

    {
        __half* outb = out + (long)b * 180 * 768 + h * 64;
#pragma unroll
        for (int nt = 0; nt < 8; nt++) {
            float acc[4] = {0.f, 0.f, 0.f, 0.f};
#pragma unroll
            for (int ktp = 0; ktp < 6; ktp++) {
                uint32_t bv4[4];
                ldsm_x4t(bv4, smem_u32(&V16[(ktp * 32 + trow) * 72 + nt * 8]));
                mma_f16(acc, P[2 * ktp], bv4, acc);
                mma_f16(acc, P[2 * ktp + 1], bv4 + 2, acc);
            }
            int row = r0 + g4;
            long col = nt * 8 + 2 * c4;
            if (row < 180)
                *(uint32_t*)(outb + (long)row * 768 + col) = packh2(acc[0], acc[1]);
            if (row + 8 < 180)
                *(uint32_t*)(outb + (long)(row + 8) * 768 + col) = packh2(acc[2], acc[3]);
        }
    }
}

// ---------------- fused tail (x4 ldsm): outproj + LN2 + MLP + next LN1 ----------------
#define T_WS   0
#define T_ASHS 49664
#define T_W1S  58880
#define T_W2S  77312
#define TAIL_SMEM 188416

__global__ void __launch_bounds__(256) tail_fused_k(const __half* __restrict__ ao,
                                                    const __half* __restrict__ owh,
                                                    const float* __restrict__ ob,
                                                    const float* __restrict__ x,
                                                    const __half* __restrict__ w1h,
                                                    const float* __restrict__ b1,
                                                    const __half* __restrict__ w2h,
                                                    const float* __restrict__ b2,
                                                    const float* __restrict__ lng,
                                                    const float* __restrict__ lnb,
                                                    float* __restrict__ outx,
                                                    const float* __restrict__ lng1n,
                                                    const float* __restrict__ lnb1n,
                                                    __half* __restrict__ h16out) {
    extern __shared__ __half smt[];
    __half* Ws  = smt + T_WS;
    __half* As  = smt + T_ASHS;
    __half* W1s = smt + T_W1S;
    __half* W2s = smt + T_W2S;

    const int tid = threadIdx.x, lane = tid & 31, w = tid >> 5;
    const int g4 = lane >> 2, c4 = lane & 3;
    const int lmrow = lane & 15, lmk = (lane >> 4) * 8;
    const int m4 = lane >> 3, r8 = lane & 7;
    const int xrow = ((m4 >> 1) << 3) + r8, xk = (m4 & 1) * 8;
    const int r0 = w * 16;

    for (int idx = tid; idx < 64 * 96; idx += 256) {
        int n = idx / 96, q = idx % 96;
        *(uint4*)&Ws[n * 776 + q * 8] = *(const uint4*)(owh + n * 768 + q * 8);
    }
    for (int idx = tid; idx < 256 * 8; idx += 256) {
        int n = idx >> 3, q = idx & 7;
        *(uint4*)&W1s[n * 72 + q * 8] = *(const uint4*)(w1h + n * 64 + q * 8);
    }
    for (int idx = tid; idx < 64 * 32; idx += 256) {
        int n = idx >> 5, q = idx & 31;
        *(uint4*)&W2s[n * 264 + q * 8] = *(const uint4*)(w2h + n * 256 + q * 8);
    }
    __syncthreads();

    const int ar = tid >> 1, apart = (tid & 1) * 32;

    for (int c = 0; c < 3; c++) {
        const long bm = ((long)blockIdx.x * 3 + c) * 128;

        float acc[8][4];
#pragma unroll
        for (int nt = 0; nt < 8; nt++)
#pragma unroll
            for (int i = 0; i < 4; i++) acc[nt][i] = 0.f;

        for (int kc = 0; kc < 12; kc++) {
            {
                const uint4* src = (const uint4*)(ao + (bm + ar) * 768 + kc * 64 + apart);
                uint4* dst = (uint4*)&As[ar * 72 + apart];
                dst[0] = src[0]; dst[1] = src[1]; dst[2] = src[2]; dst[3] = src[3];
            }
            __syncwarp();
            uint32_t afr[4][4];
#pragma unroll
            for (int ks = 0; ks < 4; ks++)
                ldsm_x4(afr[ks], smem_u32(&As[(r0 + lmrow) * 72 + ks * 16 + lmk]));
#pragma unroll
            for (int ntp = 0; ntp < 4; ntp++) {
#pragma unroll
                for (int ks = 0; ks < 4; ks++) {
                    uint32_t bf4[4];
                    ldsm_x4(bf4, smem_u32(&Ws[(ntp * 16 + xrow) * 776 + kc * 64 + ks * 16 + xk]));
                    mma_f16(acc[2 * ntp], afr[ks], bf4, acc[2 * ntp]);
                    mma_f16(acc[2 * ntp + 1], afr[ks], bf4 + 2, acc[2 * ntp + 1]);
                }
            }
            __syncwarp();
        }

        float xres[8][4];
#pragma unroll
        for (int nt = 0; nt < 8; nt++) {
            int col = nt * 8 + 2 * c4;
            float b0 = ob[col], b1v = ob[col + 1];
#pragma unroll
            for (int half = 0; half < 2; half++) {
                long row = bm + r0 + g4 + 8 * half;
                float2 r = *(const float2*)(x + row * 64 + col);
                xres[nt][2 * half]     = acc[nt][2 * half] + b0 + r.x;
                xres[nt][2 * half + 1] = acc[nt][2 * half + 1] + b1v + r.y;
            }
        }
        {
            float s0 = 0.f, s1 = 0.f;
#pragma unroll
            for (int nt = 0; nt < 8; nt++) {
                s0 += xres[nt][0] + xres[nt][1];
                s1 += xres[nt][2] + xres[nt][3];
            }
            s0 += __shfl_xor_sync(0xffffffffu, s0, 1);
            s0 += __shfl_xor_sync(0xffffffffu, s0, 2);
            s1 += __shfl_xor_sync(0xffffffffu, s1, 1);
            s1 += __shfl_xor_sync(0xffffffffu, s1, 2);
            float m0 = s0 * (1.f / 64.f), m1 = s1 * (1.f / 64.f);
            float q0 = 0.f, q1 = 0.f;
#pragma unroll
            for (int nt = 0; nt < 8; nt++) {
                float d0 = xres[nt][0] - m0, d1 = xres[nt][1] - m0;
                float d2 = xres[nt][2] - m1, d3 = xres[nt][3] - m1;
                q0 += d0 * d0 + d1 * d1;
                q1 += d2 * d2 + d3 * d3;
            }
            q0 += __shfl_xor_sync(0xffffffffu, q0, 1);
            q0 += __shfl_xor_sync(0xffffffffu, q0, 2);
            q1 += __shfl_xor_sync(0xffffffffu, q1, 1);
            q1 += __shfl_xor_sync(0xffffffffu, q1, 2);
            float rs0 = rsqrtf(q0 * (1.f / 64.f) + 1e-5f);
            float rs1 = rsqrtf(q1 * (1.f / 64.f) + 1e-5f);
#pragma unroll
            for (int nt = 0; nt < 8; nt++) {
                int col = nt * 8 + 2 * c4;
                float g0 = lng[col], g1 = lng[col + 1];
                float be0 = lnb[col], be1 = lnb[col + 1];
                float h0 = (xres[nt][0] - m0) * rs0 * g0 + be0;
                float h1 = (xres[nt][1] - m0) * rs0 * g1 + be1;
                float h2 = (xres[nt][2] - m1) * rs1 * g0 + be0;
                float h3 = (xres[nt][3] - m1) * rs1 * g1 + be1;
                *(uint32_t*)&As[(r0 + g4) * 72 + col]     = packh2(h0, h1);
                *(uint32_t*)&As[(r0 + g4 + 8) * 72 + col] = packh2(h2, h3);
            }
        }
        __syncwarp();

        uint32_t afg[16][4];
        {
            uint32_t afr[4][4];
#pragma unroll
            for (int ks = 0; ks < 4; ks++)
                ldsm_x4(afr[ks], smem_u32(&As[(r0 + lmrow) * 72 + ks * 16 + lmk]));
#pragma unroll
            for (int kt = 0; kt < 16; kt++) {
                float d0[4] = {0.f, 0.f, 0.f, 0.f}, d1[4] = {0.f, 0.f, 0.f, 0.f};
#pragma unroll
                for (int ks = 0; ks < 4; ks++) {
                    uint32_t bf4[4];
                    ldsm_x4(bf4, smem_u32(&W1s[(kt * 16 + xrow) * 72 + ks * 16 + xk]));
                    mma_f16(d0, afr[ks], bf4, d0);
                    mma_f16(d1, afr[ks], bf4 + 2, d1);
                }
                int col0 = (2 * kt) * 8 + 2 * c4, col1 = (2 * kt + 1) * 8 + 2 * c4;
                float a0 = d0[0] + b1[col0],     a1 = d0[1] + b1[col0 + 1];
                float a2 = d0[2] + b1[col0],     a3 = d0[3] + b1[col0 + 1];
                float a4 = d1[0] + b1[col1],     a5 = d1[1] + b1[col1 + 1];
                float a6 = d1[2] + b1[col1],     a7 = d1[3] + b1[col1 + 1];
                a0 = 0.5f * a0 * (1.f + erff(a0 * 0.70710678118654752f));
                a1 = 0.5f * a1 * (1.f + erff(a1 * 0.70710678118654752f));
                a2 = 0.5f * a2 * (1.f + erff(a2 * 0.70710678118654752f));
                a3 = 0.5f * a3 * (1.f + erff(a3 * 0.70710678118654752f));
                a4 = 0.5f * a4 * (1.f + erff(a4 * 0.70710678118654752f));
                a5 = 0.5f * a5 * (1.f + erff(a5 * 0.70710678118654752f));
                a6 = 0.5f * a6 * (1.f + erff(a6 * 0.70710678118654752f));
                a7 = 0.5f * a7 * (1.f + erff(a7 * 0.70710678118654752f));
                afg[kt][0] = packh2(a0, a1);
                afg[kt][1] = packh2(a2, a3);
                afg[kt][2] = packh2(a4, a5);
                afg[kt][3] = packh2(a6, a7);
            }
        }

        float xf[8][4];
#pragma unroll
        for (int nt = 0; nt < 8; nt++) {
            float a2c[4] = {0.f, 0.f, 0.f, 0.f};
#pragma unroll
            for (int ktp = 0; ktp < 8; ktp++) {
                uint32_t bf4[4];
                ldsm_x4(bf4, smem_u32(&W2s[(nt * 8 + r8) * 264 + ktp * 32 + m4 * 8]));
                mma_f16(a2c, afg[2 * ktp], bf4, a2c);
                mma_f16(a2c, afg[2 * ktp + 1], bf4 + 2, a2c);
            }
            int col = nt * 8 + 2 * c4;
            float bb0 = b2[col], bb1 = b2[col + 1];
#pragma unroll
            for (int half = 0; half < 2; half++) {
                long row = bm + r0 + g4 + 8 * half;
                float v0 = a2c[2 * half] + bb0 + xres[nt][2 * half];
                float v1 = a2c[2 * half + 1] + bb1 + xres[nt][2 * half + 1];
                xf[nt][2 * half] = v0; xf[nt][2 * half + 1] = v1;
                *(float2*)(outx + row * 64 + col) = make_float2(v0, v1);
            }
        }
        if (h16out) {
            float s0 = 0.f, s1 = 0.f;
#pragma unroll
            for (int nt = 0; nt < 8; nt++) {
                s0 += xf[nt][0] + xf[nt][1];
                s1 += xf[nt][2] + xf[nt][3];
            }
            s0 += __shfl_xor_sync(0xffffffffu, s0, 1);
            s0 += __shfl_xor_sync(0xffffffffu, s0, 2);
            s1 += __shfl_xor_sync(0xffffffffu, s1, 1);
            s1 += __shfl_xor_sync(0xffffffffu, s1, 2);
            float m0 = s0 * (1.f / 64.f), m1 = s1 * (1.f / 64.f);
            float q0 = 0.f, q1 = 0.f;
#pragma unroll
            for (int nt = 0; nt < 8; nt++) {
                float d0 = xf[nt][0] - m0, d1 = xf[nt][1] - m0;
                float d2 = xf[nt][2] - m1, d3 = xf[nt][3] - m1;
                q0 += d0 * d0 + d1 * d1;
                q1 += d2 * d2 + d3 * d3;
            }
            q0 += __shfl_xor_sync(0xffffffffu, q0, 1);
            q0 += __shfl_xor_sync(0xffffffffu, q0, 2);
            q1 += __shfl_xor_sync(0xffffffffu, q1, 1);
            q1 += __shfl_xor_sync(0xffffffffu, q1, 2);
            float rs0 = rsqrtf(q0 * (1.f / 64.f) + 1e-5f);
            float rs1 = rsqrtf(q1 * (1.f / 64.f) + 1e-5f);
#pragma unroll
            for (int nt = 0; nt < 8; nt++) {
                int col = nt * 8 + 2 * c4;
                float g0 = lng1n[col], g1 = lng1n[col + 1];
                float be0 = lnb1n[col], be1 = lnb1n[col + 1];
                long row0g = bm + r0 + g4;
                *(uint32_t*)(h16out + row0g * 64 + col) =
                    packh2((xf[nt][0] - m0) * rs0 * g0 + be0, (xf[nt][1] - m0) * rs0 * g1 + be1);
                *(uint32_t*)(h16out + (row0g + 8) * 64 + col) =
                    packh2((xf[nt][2] - m1) * rs1 * g0 + be0, (xf[nt][3] - m1) * rs1 * g1 + be1);
            }
        }
        __syncwarp();
    }
}

// ---------------- primary caps: gather + squash ----------------
__global__ void caps_squash_k(const float* __restrict__ pc, float* __restrict__ caps) {
    int idx = blockIdx.x * blockDim.x + threadIdx.x;
    if (idx >= 256 * 1024) return;
    int i = idx & 1023, b = idx >> 10;
    int i32 = i >> 5, y = (i >> 3) & 3, xq = i & 7;
    const float* src = pc + (((long)b * 4 + y) * 8 + xq) * 256 + i32 * 8;
    float t[8];
    float l2 = 0.f;
#pragma unroll
    for (int e = 0; e < 8; e++) { t[e] = src[e]; l2 += t[e] * t[e]; }
    float sc = sqrtf(l2) / (1.f + l2);
#pragma unroll
    for (int e = 0; e < 8; e++) caps[(long)idx * 8 + e] = t[e] * sc;
}

// ---------------- capsule predictions (fp16 out) ----------------
__global__ void caps_u_k(const float* __restrict__ caps, const float* __restrict__ cw,
                         __half* __restrict__ u) {
    __shared__ float w_s[8 * 48];
    int i = blockIdx.x;
    for (int t = threadIdx.x; t < 384; t += 256) w_s[t] = cw[(long)i * 384 + t];
    __syncthreads();
    int b = threadIdx.x;
    float ce[8];
    const float* cp = caps + ((long)b * 1024 + i) * 8;
#pragma unroll
    for (int e = 0; e < 8; e++) ce[e] = cp[e];
    __half* up = u + ((long)b * 1024 + i) * 48;
#pragma unroll 4
    for (int o = 0; o < 48; o++) {
        float s = 0.f;
#pragma unroll
        for (int e = 0; e < 8; e++) s = fmaf(ce[e], w_s[e * 48 + o], s);
        up[o] = __float2half(s);
    }
}

// ---------------- dynamic routing ----------------
#define ROUT_SMEM ((49152 + 3072 + 96) * 4)
__global__ void __launch_bounds__(256) routing_k(const __half* __restrict__ u,
                                                 const float* __restrict__ br,
                                                 float* __restrict__ out) {
    extern __shared__ float smr[];
    float* us = smr;
    float* bb = smr + 49152;
    float* S  = bb + 3072;
    float* v  = S + 48;
    int b = blockIdx.x, tid = threadIdx.x, lane = tid & 31;
    const __half* ub = u + (long)b * 1024 * 48;
    for (int i = tid; i < 49152; i += 256) us[i] = __half2float(ub[i]);
    for (int i = tid; i < 3072; i += 256) bb[i] = br[i];
    __syncthreads();

    for (int it = 0; it < 4; it++) {
        if (tid < 48) S[tid] = 0.f;
        __syncthreads();
        float acc[48];
#pragma unroll
        for (int o = 0; o < 48; o++) acc[o] = 0.f;
        for (int i = tid; i < 1024; i += 256) {
            float b0 = bb[i * 3], b1 = bb[i * 3 + 1], b2 = bb[i * 3 + 2];
            float m = fmaxf(b0, fmaxf(b1, b2));
            float e0 = expf(b0 - m), e1 = expf(b1 - m), e2 = expf(b2 - m);
            float inv = 1.f / (e0 + e1 + e2);
            float c[3] = {e0 * inv, e1 * inv, e2 * inv};
            const float* up = &us[i * 48];
#pragma unroll
            for (int j = 0; j < 3; j++)
#pragma unroll
                for (int o = 0; o < 16; o++)
                    acc[j * 16 + o] = fmaf(c[j], up[j * 16 + o], acc[j * 16 + o]);
        }
#pragma unroll
        for (int o = 0; o < 48; o++) {
            float s = acc[o];
#pragma unroll
            for (int d = 16; d; d >>= 1) s += __shfl_xor_sync(0xffffffffu, s, d);
            if (lane == 0) atomicAdd(&S[o], s);
        }
        __syncthreads();
        if (tid < 3) {
            float l2 = 0.f;
            for (int o = 0; o < 16; o++) { float t = S[tid * 16 + o]; l2 += t * t; }
            float sc = sqrtf(l2) / (1.f + l2);
            for (int o = 0; o < 16; o++) v[tid * 16 + o] = S[tid * 16 + o] * sc;
            if (it == 3) out[b * 3 + tid] = l2 / (1.f + l2);
        }
        __syncthreads();
        if (it < 3) {
            for (int i = tid; i < 1024; i += 256) {
                const float* up = &us[i * 48];
#pragma unroll
                for (int j = 0; j < 3; j++) {
                    float s = 0.f;
#pragma unroll
                    for (int o = 0; o < 16; o++) s = fmaf(up[j * 16 + o], v[j * 16 + o], s);
                    bb[i * 3 + j] += s;
                }
            }
            __syncthreads();
        }
    }
}

// ---------------- host ----------------
extern "C" void kernel_launch(void* const* d_in, const int* in_sizes, int n_in,
                              void* d_out, int out_size) {
    const float* x_in    = (const float*)d_in[0];
    const float* conv1_w = (const float*)d_in[1];
    const float* conv2_w = (const float*)d_in[2];
    const float* pos_emb = (const float*)d_in[3];
    const float* ln1_g   = (const float*)d_in[4];
    const float* ln1_b   = (const float*)d_in[5];
    const float* qkv_w   = (const float*)d_in[6];
    const float* out_w   = (const float*)d_in[7];
    const float* out_b   = (const float*)d_in[8];
    const float* ln2_g   = (const float*)d_in[9];
    const float* ln2_b   = (const float*)d_in[10];
    const float* ff1_w   = (const float*)d_in[11];
    const float* ff1_b   = (const float*)d_in[12];
    const float* ff2_w   = (const float*)d_in[13];
    const float* ff2_b   = (const float*)d_in[14];
    const float* pcaps_w = (const float*)d_in[15];
    const float* pcaps_b = (const float*)d_in[16];
    const float* caps_w  = (const float*)d_in[17];
    const float* b_route = (const float*)d_in[18];
    float* out = (float*)d_out;

    float *xb, *col3, *wtp, *pc, *caps;
    __half *col1h, *y1h, *p1h, *y2h, *h16g, *aoh, *uh, *qh, *owh, *w1h, *w2h, *cw1h, *cw2h;
    cudaGetSymbolAddress((void**)&col1h, g_col1h);
    cudaGetSymbolAddress((void**)&y1h,  g_y1h);
    cudaGetSymbolAddress((void**)&p1h,  g_p1h);
    cudaGetSymbolAddress((void**)&y2h,  g_y2h);
    cudaGetSymbolAddress((void**)&xb,   g_x);
    cudaGetSymbolAddress((void**)&h16g, g_h16);
    cudaGetSymbolAddress((void**)&aoh,  g_aoh);
    cudaGetSymbolAddress((void**)&col3, g_col3);
    cudaGetSymbolAddress((void**)&wtp,  g_wtp);
    cudaGetSymbolAddress((void**)&pc,   g_pc);
    cudaGetSymbolAddress((void**)&caps, g_caps);
    cudaGetSymbolAddress((void**)&uh,   g_uh);
    cudaGetSymbolAddress((void**)&qh,   g_qh);
    cudaGetSymbolAddress((void**)&owh,  g_owh);
    cudaGetSymbolAddress((void**)&w1h,  g_w1h);
    cudaGetSymbolAddress((void**)&w2h,  g_w2h);
    cudaGetSymbolAddress((void**)&cw1h, g_cw1h);
    cudaGetSymbolAddress((void**)&cw2h, g_cw2h);

    cudaFuncSetAttribute(attn_fused_k, cudaFuncAttributeMaxDynamicSharedMemorySize, ATTNH_SMEM);
    cudaFuncSetAttribute(tail_fused_k, cudaFuncAttributeMaxDynamicSharedMemorySize, TAIL_SMEM);
    cudaFuncSetAttribute(hconv1_k,     cudaFuncAttributeMaxDynamicSharedMemorySize, HC1_SMEM);
    cudaFuncSetAttribute(hconv2_k,     cudaFuncAttributeMaxDynamicSharedMemorySize, HC2_SMEM);
    cudaFuncSetAttribute(routing_k,    cudaFuncAttributeMaxDynamicSharedMemorySize, ROUT_SMEM);

    prep_qkv_k<<<CDIV(12 * 12 * 3 * 4096, 256), 256>>>(qkv_w, qh);
    prep_ow_k <<<CDIV(12 * 64 * 768, 256), 256>>>(out_w, owh);
    prep_w1_k <<<CDIV(12 * 256 * 64, 256), 256>>>(ff1_w, w1h);
    prep_w2_k <<<CDIV(12 * 64 * 256, 256), 256>>>(ff2_w, w2h);
    prep_cw1_k<<<CDIV(64 * 32, 256), 256>>>(conv1_w, cw1h);
    prep_cw2_k<<<CDIV(64 * 576, 256), 256>>>(conv2_w, cw2h);

    // ---- ConvEmbed (fp16 MMA, vectorized im2col + half2 pools) ----
    im2col1v_k<<<CDIV(737280, 256), 256>>>(x_in, col1h);
    hconv1_k<<<737280 / 128, 256, HC1_SMEM>>>(col1h, cw1h, y1h);
    maxpool_h2_k<<<(int)CDIV((long)256 * 20 * 36 * 32, 256), 256>>>(
        (const __half2*)y1h, (__half2*)p1h, 256, 40, 72, 20, 36);
    hconv2_k<<<184320 / 128, 256, HC2_SMEM>>>(p1h, cw2h, y2h);
    maxpool_h2f_k<<<(int)CDIV((long)256 * 10 * 18 * 32, 256), 256>>>(
        (const __half2*)y2h, xb, 256, 20, 36, 10, 18, pos_emb);

    // ---- Transformer: 12 shared layers applied twice, LN1 fused into tail ----
    const int M = 46080;
    ln1h_k<<<M / 8, 256>>>(xb, ln1_g, ln1_b, h16g, M);
    for (int pass = 0; pass < 2; pass++) {
        for (int l = 0; l < 12; l++) {
            bool last = (pass == 1) && (l == 11);
            int ln = (l + 1) % 12;
            attn_fused_k<<<256 * 12, 384, ATTNH_SMEM>>>(h16g, qh + (long)l * 147456, aoh);
            tail_fused_k<<<120, 256, TAIL_SMEM>>>(aoh, owh + (long)l * 49152, out_b + l * 64,
                                                  xb, w1h + (long)l * 16384, ff1_b + l * 256,
                                                  w2h + (long)l * 16384, ff2_b + l * 64,
                                                  ln2_g + l * 64, ln2_b + l * 64, xb,
                                                  last ? nullptr : ln1_g + ln * 64,
                                                  last ? nullptr : ln1_b + ln * 64,
                                                  last ? nullptr : h16g);
        }
    }

    // ---- PrimaryCaps + routing (R14 path) ----
    im2col3_k<<<(int)CDIV((long)8192 * 576, 256), 256>>>(xb, col3);
    wtrans_hwc<<<CDIV(256 * 576, 256), 256>>>(pcaps_w, wtp, 256, 64);
    tgemm_k<2><<<dim3(256 / 64, 8192 / 128), 256>>>(col3, wtp, pcaps_b, pc, 8192, 256, 576);
    caps_squash_k<<<CDIV(256 * 1024, 256), 256>>>(pc, caps);
    caps_u_k<<<1024, 256>>>(caps, caps_w, uh);
    routing_k<<<256, 256, ROUT_SMEM>>>(uh, b_route, out);
}

// round 17
// speedup vs baseline: 1.0263x; 1.0015x over previous
#include <cuda_runtime.h>
#include <cuda_fp16.h>
#include <math.h>
#include <stdint.h>

#define CDIV(a,b) (((a)+(b)-1)/(b))

// ---------------- static scratch (no allocations allowed) ----------------
__device__ __half g_y1h [737280 * 64];
__device__ __half g_p1h [184320 * 64];
__device__ __half g_y2h [184320 * 64];
__device__ float  g_x   [46080 * 64];
__device__ __half g_h16 [46080 * 64];
__device__ __half g_aoh [46080 * 768];
__device__ float  g_col3[8192 * 576];
__device__ float  g_wtp [576 * 256];
__device__ float  g_pc  [8192 * 256];
__device__ __half g_uh  [256 * 1024 * 48];
__device__ __half g_qh  [12 * 12 * 3 * 64 * 64];
__device__ __half g_owh [12 * 64 * 768];
__device__ __half g_w1h [12 * 256 * 64];
__device__ __half g_w2h [12 * 64 * 256];
__device__ __half g_cw1h[64 * 32];
__device__ __half g_cw2h[64 * 576];

// ---------------- weight prep ----------------
__global__ void prep_qkv_k(const float* __restrict__ qw, __half* __restrict__ qh) {
    int idx = blockIdx.x * 256 + threadIdx.x;
    if (idx >= 12 * 12 * 3 * 4096) return;
    int k = idx & 63, n = (idx >> 6) & 63;
    int rest = idx >> 12;
    int mat = rest % 3; rest /= 3;
    int h = rest % 12, l = rest / 12;
    int moff = (mat == 0) ? 768 : (mat == 1) ? 1536 : 0;
    qh[idx] = __float2half(qw[(long)l * 64 * 2304 + (long)k * 2304 + moff + h * 64 + n]);
}
__global__ void prep_ow_k(const float* __restrict__ ow, __half* __restrict__ oh) {
    int idx = blockIdx.x * 256 + threadIdx.x;
    if (idx >= 12 * 64 * 768) return;
    int k = idx % 768, n = (idx / 768) % 64, l = idx / 49152;
    oh[idx] = __float2half(ow[(long)l * 49152 + (long)k * 64 + n]);
}
__global__ void prep_w1_k(const float* __restrict__ w1, __half* __restrict__ o) {
    int idx = blockIdx.x * 256 + threadIdx.x;
    if (idx >= 12 * 256 * 64) return;
    int k = idx & 63, n = (idx >> 6) & 255, l = idx >> 14;
    o[idx] = __float2half(w1[(long)l * 16384 + (long)k * 256 + n]);
}
__global__ void prep_w2_k(const float* __restrict__ w2, __half* __restrict__ o) {
    int idx = blockIdx.x * 256 + threadIdx.x;
    if (idx >= 12 * 64 * 256) return;
    int k = idx & 255, n = (idx >> 8) & 63, l = idx >> 14;
    o[idx] = __float2half(w2[(long)l * 16384 + (long)k * 64 + n]);
}
__global__ void prep_cw1_k(const float* __restrict__ w, __half* __restrict__ o) {
    int idx = blockIdx.x * 256 + threadIdx.x;
    if (idx >= 64 * 32) return;
    int k = idx & 31, n = idx >> 5;
    o[idx] = __float2half(k < 27 ? w[n * 27 + k] : 0.f);
}
__global__ void prep_cw2_k(const float* __restrict__ w, __half* __restrict__ o) {
    int idx = blockIdx.x * 256 + threadIdx.x;
    if (idx >= 64 * 576) return;
    int kk = idx % 576, n = idx / 576;
    int ci = kk & 63, tap = kk >> 6;
    o[idx] = __float2half(w[n * 576 + ci * 9 + tap]);
}

__global__ void im2col3_k(const float* __restrict__ tk, float* __restrict__ col) {
    long idx = (long)blockIdx.x * blockDim.x + threadIdx.x;
    const long total = (long)8192 * 576;
    if (idx >= total) return;
    int kk = (int)(idx % 576);
    long m = idx / 576;
    int ow = (int)(m % 8);
    int t  = (int)(m / 8);
    int oh = t % 4;
    int b  = t / 4;
    int ci = kk % 64;
    int kw = (kk / 64) % 3;
    int kh = kk / 192;
    int ih = oh * 2 + kh, iw = ow * 2 + kw;
    col[idx] = tk[((long)b * 180 + ih * 18 + iw) * 64 + ci];
}

__global__ void wtrans_hwc(const float* __restrict__ w, float* __restrict__ wt, int O, int CI) {
    int K = CI * 9;
    int i = blockIdx.x * blockDim.x + threadIdx.x;
    if (i >= O * K) return;
    int o = i / K, r = i % K;
    int ci = r / 9, kh = (r % 9) / 3, kw = r % 3;
    wt[((kh * 3 + kw) * CI + ci) * O + o] = w[i];
}

// ---------------- tf32 helpers ----------------
__device__ __forceinline__ float f2tf(float f) {
    uint32_t r;
    asm("cvt.rna.tf32.f32 %0, %1;" : "=r"(r) : "f"(f));
    return __uint_as_float(r);
}
__device__ __forceinline__ void mma_tf32(float d[4], const uint32_t a[4], const uint32_t b[2],
                                         const float c[4]) {
    asm("mma.sync.aligned.m16n8k8.row.col.f32.tf32.tf32.f32 "
        "{%0,%1,%2,%3},{%4,%5,%6,%7},{%8,%9},{%10,%11,%12,%13};"
        : "=f"(d[0]), "=f"(d[1]), "=f"(d[2]), "=f"(d[3])
        : "r"(a[0]), "r"(a[1]), "r"(a[2]), "r"(a[3]), "r"(b[0]), "r"(b[1]),
          "f"(c[0]), "f"(c[1]), "f"(c[2]), "f"(c[3]));
}

// ---------------- fp16 mma helpers ----------------
__device__ __forceinline__ uint32_t smem_u32(const void* p) {
    return (uint32_t)__cvta_generic_to_shared(p);
}
__device__ __forceinline__ void ldsm_x4(uint32_t r[4], uint32_t addr) {
    asm volatile("ldmatrix.sync.aligned.m8n8.x4.shared.b16 {%0,%1,%2,%3}, [%4];"
        : "=r"(r[0]), "=r"(r[1]), "=r"(r[2]), "=r"(r[3]) : "r"(addr));
}
__device__ __forceinline__ void ldsm_x2(uint32_t r[2], uint32_t addr) {
    asm volatile("ldmatrix.sync.aligned.m8n8.x2.shared.b16 {%0,%1}, [%2];"
        : "=r"(r[0]), "=r"(r[1]) : "r"(addr));
}
__device__ __forceinline__ void ldsm_x4t(uint32_t r[4], uint32_t addr) {
    asm volatile("ldmatrix.sync.aligned.m8n8.x4.trans.shared.b16 {%0,%1,%2,%3}, [%4];"
        : "=r"(r[0]), "=r"(r[1]), "=r"(r[2]), "=r"(r[3]) : "r"(addr));
}
__device__ __forceinline__ void mma_f16(float d[4], const uint32_t a[4], const uint32_t b[2],
                                        const float c[4]) {
    asm volatile("mma.sync.aligned.m16n8k16.row.col.f32.f16.f16.f32 "
        "{%0,%1,%2,%3},{%4,%5,%6,%7},{%8,%9},{%10,%11,%12,%13};"
        : "=f"(d[0]), "=f"(d[1]), "=f"(d[2]), "=f"(d[3])
        : "r"(a[0]), "r"(a[1]), "r"(a[2]), "r"(a[3]), "r"(b[0]), "r"(b[1]),
          "f"(c[0]), "f"(c[1]), "f"(c[2]), "f"(c[3]));
}
__device__ __forceinline__ uint32_t packh2(float a, float b) {
    __half2 h = __floats2half2_rn(a, b);
    return *(uint32_t*)&h;
}

// ---------------- tf32 tensor-core GEMM (pcaps) ----------------
template <int EPI>
__global__ void __launch_bounds__(256) tgemm_k(const float* __restrict__ A, const float* __restrict__ Bm,
                                               const float* __restrict__ bias,
                                               float* __restrict__ C, int M, int N, int K) {
    __shared__ float As[128 * 36];
    __shared__ float Bs[32 * 68];
    const int bm = blockIdx.y * 128, bn = blockIdx.x * 64;
    const int tid = threadIdx.x, lane = tid & 31, w = tid >> 5;
    const int g4 = lane >> 2, c4 = lane & 3;
    const int wm = (w & 3) * 32, wn = (w >> 2) * 32;

    float acc[2][4][4];
#pragma unroll
    for (int mt = 0; mt < 2; mt++)
#pragma unroll
        for (int nt = 0; nt < 4; nt++)
#pragma unroll
            for (int i = 0; i < 4; i++) acc[mt][nt][i] = 0.f;

    const int ar = tid >> 1, akb = (tid & 1) * 16;
    const int bk = tid >> 3, bn0 = (tid & 7) * 8;
    const float* Arow = A + (long)(bm + ar) * K;

    for (int k0 = 0; k0 < K; k0 += 32) {
        float4 av[4], bv[2];
#pragma unroll
        for (int i = 0; i < 4; i++) {
            int gk = k0 + akb + 4 * i;
            av[i] = (gk + 4 <= K) ? *(const float4*)(Arow + gk) : make_float4(0.f, 0.f, 0.f, 0.f);
        }
        {
            int gk = k0 + bk;
            if (gk < K) {
                bv[0] = *(const float4*)(Bm + (long)gk * N + bn + bn0);
                bv[1] = *(const float4*)(Bm + (long)gk * N + bn + bn0 + 4);
            } else {
                bv[0] = make_float4(0.f, 0.f, 0.f, 0.f);
                bv[1] = bv[0];
            }
        }
        __syncthreads();
#pragma unroll
        for (int i = 0; i < 4; i++) {
            float* p = &As[ar * 36 + akb + 4 * i];
            p[0] = f2tf(av[i].x); p[1] = f2tf(av[i].y); p[2] = f2tf(av[i].z); p[3] = f2tf(av[i].w);
        }
        {
            float* p = &Bs[bk * 68 + bn0];
            p[0] = f2tf(bv[0].x); p[1] = f2tf(bv[0].y); p[2] = f2tf(bv[0].z); p[3] = f2tf(bv[0].w);
            p[4] = f2tf(bv[1].x); p[5] = f2tf(bv[1].y); p[6] = f2tf(bv[1].z); p[7] = f2tf(bv[1].w);
        }
        __syncthreads();
#pragma unroll
        for (int ks = 0; ks < 4; ks++) {
            uint32_t bfr[4][2], afr[2][4];
#pragma unroll
            for (int nt = 0; nt < 4; nt++) {
                int col = wn + nt * 8 + g4;
                bfr[nt][0] = __float_as_uint(Bs[(ks * 8 + c4) * 68 + col]);
                bfr[nt][1] = __float_as_uint(Bs[(ks * 8 + c4 + 4) * 68 + col]);
            }
#pragma unroll
            for (int mt = 0; mt < 2; mt++) {
                int base = (wm + mt * 16 + g4) * 36 + ks * 8 + c4;
                afr[mt][0] = __float_as_uint(As[base]);
                afr[mt][1] = __float_as_uint(As[base + 8 * 36]);
                afr[mt][2] = __float_as_uint(As[base + 4]);
                afr[mt][3] = __float_as_uint(As[base + 8 * 36 + 4]);
            }
#pragma unroll
            for (int mt = 0; mt < 2; mt++)
#pragma unroll
                for (int nt = 0; nt < 4; nt++)
                    mma_tf32(acc[mt][nt], afr[mt], bfr[nt], acc[mt][nt]);
        }
        __syncthreads();
    }

#pragma unroll
    for (int nt = 0; nt < 4; nt++) {
        int col = bn + wn + nt * 8 + 2 * c4;
        float b0 = 0.f, b1 = 0.f;
        if (EPI >= 2) { b0 = bias[col]; b1 = bias[col + 1]; }
#pragma unroll
        for (int mt = 0; mt < 2; mt++) {
#pragma unroll
            for (int half = 0; half < 2; half++) {
                long row = bm + wm + mt * 16 + g4 + 8 * half;
                float v0 = acc[mt][nt][2 * half], v1 = acc[mt][nt][2 * half + 1];
                if (EPI == 1) { v0 = fmaxf(v0, 0.f); v1 = fmaxf(v1, 0.f); }
                if (EPI >= 2) { v0 += b0; v1 += b1; }
                *(float2*)(C + row * N + col) = make_float2(v0, v1);
            }
        }
    }
}

// ---------------- conv1 direct (fused im2col): fp16 GEMM ----------------
#define HC1_SMEM ((64 * 40 + 128 * 40) * 2)
__global__ void __launch_bounds__(256) hconv1d_k(const float* __restrict__ x,
                                                 const __half* __restrict__ wch,
                                                 __half* __restrict__ y1) {
    extern __shared__ __half sm1[];
    __half* Ws = sm1;               // [64 n][40 k]
    __half* As = sm1 + 64 * 40;     // [128 m][40 k]

    const int bm = blockIdx.x * 128;
    const int tid = threadIdx.x, lane = tid & 31, w = tid >> 5;
    const int g4 = lane >> 2, c4 = lane & 3;
    const int lmrow = lane & 15, lmk = (lane >> 4) * 8;
    const int b2row = lane & 7, b2k = ((lane >> 3) & 1) * 8;
    const int r0 = w * 16;

    for (int idx = tid; idx < 64 * 4; idx += 256) {
        int n = idx >> 2, q = idx & 3;
        *(uint4*)&Ws[n * 40 + q * 8] = *(const uint4*)(wch + n * 32 + q * 8);
    }
    __syncthreads();

    // gather A directly from NCHW fp32 input (27 taps + 5 zero pad)
    const int ar = tid >> 1, part = tid & 1;
    {
        int m = bm + ar;
        int ow = m % 72;
        int t  = m / 72;
        int oh = t % 40;
        int b  = t / 40;
#pragma unroll
        for (int k = part * 16; k < part * 16 + 16; k++) {
            float v = 0.f;
            if (k < 27) {
                int ci = k / 9, kh = (k % 9) / 3, kw = k % 3;
                int ih = oh + kh - 1, iw = ow + kw - 1;
                if ((unsigned)ih < 40u && (unsigned)iw < 72u)
                    v = x[(((long)b * 3 + ci) * 40 + ih) * 72 + iw];
            }
            As[ar * 40 + k] = __float2half(v);
        }
    }
    __syncwarp();

    uint32_t afr[2][4];
#pragma unroll
    for (int ks = 0; ks < 2; ks++)
        ldsm_x4(afr[ks], smem_u32(&As[(r0 + lmrow) * 40 + ks * 16 + lmk]));

#pragma unroll
    for (int nt = 0; nt < 8; nt++) {
        float acc[4] = {0.f, 0.f, 0.f, 0.f};
#pragma unroll
        for (int ks = 0; ks < 2; ks++) {
            uint32_t bf[2];
            ldsm_x2(bf, smem_u32(&Ws[(nt * 8 + b2row) * 40 + ks * 16 + b2k]));
            mma_f16(acc, afr[ks], bf, acc);
        }
        int coln = nt * 8 + 2 * c4;
#pragma unroll
        for (int half = 0; half < 2; half++) {
            long row = bm + r0 + g4 + 8 * half;
            *(uint32_t*)(y1 + row * 64 + coln) =
                packh2(fmaxf(acc[2 * half], 0.f), fmaxf(acc[2 * half + 1], 0.f));
        }
    }
}

// ---------------- conv2 direct (fused im2col) ----------------
#define HC2_SMEM (64 * 584 * 2 + 128 * 72 * 2)
__global__ void __launch_bounds__(256) hconv2_k(const __half* __restrict__ p1,
                                                const __half* __restrict__ wch,
                                                __half* __restrict__ y2) {
    extern __shared__ __half smc[];
    __half* Ws = smc;
    __half* As = smc + 64 * 584;

    const int bm = blockIdx.x * 128;
    const int tid = threadIdx.x, lane = tid & 31, w = tid >> 5;
    const int g4 = lane >> 2, c4 = lane & 3;
    const int lmrow = lane & 15, lmk = (lane >> 4) * 8;
    const int m4 = lane >> 3, r8 = lane & 7;
    const int xrow = ((m4 >> 1) << 3) + r8, xk = (m4 & 1) * 8;
    const int r0 = w * 16;

    for (int idx = tid; idx < 64 * 72; idx += 256) {
        int n = idx / 72, q = idx % 72;
        *(uint4*)&Ws[n * 584 + q * 8] = *(const uint4*)(wch + n * 576 + q * 8);
    }
    __syncthreads();

    float acc[8][4];
#pragma unroll
    for (int nt = 0; nt < 8; nt++)
#pragma unroll
        for (int i = 0; i < 4; i++) acc[nt][i] = 0.f;

    const int ar = tid >> 1, apart = (tid & 1) * 32;
    const int m = bm + ar;
    const int bidx = m / 720, rem = m % 720;
    const int oh = rem / 36, owp = rem % 36;

#pragma unroll
    for (int kc = 0; kc < 9; kc++) {
        int kh = kc / 3, kw = kc % 3;
        int ih = oh + kh - 1, iw = owp + kw - 1;
        uint4 v[4];
        if ((unsigned)ih < 20u && (unsigned)iw < 36u) {
            const uint4* src = (const uint4*)(p1 + (((long)(bidx * 20 + ih)) * 36 + iw) * 64 + apart);
            v[0] = src[0]; v[1] = src[1]; v[2] = src[2]; v[3] = src[3];
        } else {
            v[0] = make_uint4(0, 0, 0, 0); v[1] = v[0]; v[2] = v[0]; v[3] = v[0];
        }
        uint4* dst = (uint4*)&As[ar * 72 + apart];
        dst[0] = v[0]; dst[1] = v[1]; dst[2] = v[2]; dst[3] = v[3];
        __syncwarp();
        uint32_t afr[4][4];
#pragma unroll
        for (int ks = 0; ks < 4; ks++)
            ldsm_x4(afr[ks], smem_u32(&As[(r0 + lmrow) * 72 + ks * 16 + lmk]));
#pragma unroll
        for (int ntp = 0; ntp < 4; ntp++) {
#pragma unroll
            for (int ks = 0; ks < 4; ks++) {
                uint32_t bf4[4];
                ldsm_x4(bf4, smem_u32(&Ws[(ntp * 16 + xrow) * 584 + kc * 64 + ks * 16 + xk]));
                mma_f16(acc[2 * ntp], afr[ks], bf4, acc[2 * ntp]);
                mma_f16(acc[2 * ntp + 1], afr[ks], bf4 + 2, acc[2 * ntp + 1]);
            }
        }
        __syncwarp();
    }

#pragma unroll
    for (int nt = 0; nt < 8; nt++) {
        int col = nt * 8 + 2 * c4;
#pragma unroll
        for (int half = 0; half < 2; half++) {
            long row = bm + r0 + g4 + 8 * half;
            *(uint32_t*)(y2 + row * 64 + col) =
                packh2(fmaxf(acc[nt][2 * half], 0.f), fmaxf(acc[nt][2 * half + 1], 0.f));
        }
    }
}

// ---------------- maxpool fp16->fp16, 2 channels per thread ----------------
__global__ void maxpool_h2_k(const __half2* __restrict__ in, __half2* __restrict__ out,
                             int Bn, int IH, int IW, int OH, int OW) {
    long idx = (long)blockIdx.x * blockDim.x + threadIdx.x;
    long total = (long)Bn * OH * OW * 32;
    if (idx >= total) return;
    int c2 = (int)(idx & 31);
    long r = idx >> 5;
    int ow = (int)(r % OW); r /= OW;
    int oh = (int)(r % OH);
    int b  = (int)(r / OH);
    __half2 m = __floats2half2_rn(-65504.f, -65504.f);
#pragma unroll
    for (int kh = 0; kh < 3; kh++) {
        int ih = oh * 2 - 1 + kh;
        if (ih < 0 || ih >= IH) continue;
#pragma unroll
        for (int kw = 0; kw < 3; kw++) {
            int iw = ow * 2 - 1 + kw;
            if (iw < 0 || iw >= IW) continue;
            m = __hmax2(m, in[(((long)b * IH + ih) * IW + iw) * 32 + c2]);
        }
    }
    out[idx] = m;
}

// ---------------- maxpool fp16->fp32 + pos-emb, 2 channels per thread ----------------
__global__ void maxpool_h2f_k(const __half2* __restrict__ in, float* __restrict__ out,
                              int Bn, int IH, int IW, int OH, int OW,
                              const float* __restrict__ pos) {
    long idx = (long)blockIdx.x * blockDim.x + threadIdx.x;
    long total = (long)Bn * OH * OW * 32;
    if (idx >= total) return;
    int c2 = (int)(idx & 31);
    long r = idx >> 5;
    int ow = (int)(r % OW); r /= OW;
    int oh = (int)(r % OH);
    int b  = (int)(r / OH);
    float m0 = -1e30f, m1 = -1e30f;
#pragma unroll
    for (int kh = 0; kh < 3; kh++) {
        int ih = oh * 2 - 1 + kh;
        if (ih < 0 || ih >= IH) continue;
#pragma unroll
        for (int kw = 0; kw < 3; kw++) {
            int iw = ow * 2 - 1 + kw;
            if (iw < 0 || iw >= IW) continue;
            __half2 v = in[(((long)b * IH + ih) * IW + iw) * 32 + c2];
            m0 = fmaxf(m0, __low2float(v));
            m1 = fmaxf(m1, __high2float(v));
        }
    }
    float2 p = *(const float2*)(pos + (oh * OW + ow) * 64 + 2 * c2);
    long obase = (((long)b * OH + oh) * OW + ow) * 64 + 2 * c2;
    *(float2*)(out + obase) = make_float2(m0 + p.x, m1 + p.y);
}

// ---------------- LN1 -> fp16 (layer 0 only) ----------------
__global__ void ln1h_k(const float* __restrict__ x, const float* __restrict__ g,
                       const float* __restrict__ bta, __half* __restrict__ o, int ntok) {
    int warp = (blockIdx.x * blockDim.x + threadIdx.x) >> 5;
    int lane = threadIdx.x & 31;
    if (warp >= ntok) return;
    float v0 = x[(long)warp * 64 + lane];
    float v1 = x[(long)warp * 64 + 32 + lane];
    float s = v0 + v1;
#pragma unroll
    for (int off = 16; off; off >>= 1) s += __shfl_xor_sync(0xffffffffu, s, off);
    float mean = s * (1.f / 64.f);
    float d0 = v0 - mean, d1 = v1 - mean;
    float q = d0 * d0 + d1 * d1;
#pragma unroll
    for (int off = 16; off; off >>= 1) q += __shfl_xor_sync(0xffffffffu, q, off);
    float rstd = rsqrtf(q * (1.f / 64.f) + 1e-5f);
    o[(long)warp * 64 + lane]      = __float2half(d0 * rstd * g[lane] + bta[lane]);
    o[(long)warp * 64 + 32 + lane] = __float2half(d1 * rstd * g[lane + 32] + bta[lane + 32]);
}

// ---------------- fully-fused attention (x4 ldsm) ----------------
#define ATTNH_SMEM ((3 * 192 * 72 + 3 * 64 * 72) * 2)

__global__ void __launch_bounds__(384, 1) attn_fused_k(const __half* __restrict__ h16g,
                                                       const __half* __restrict__ qh,
                                                       __half* __restrict__ out) {
    extern __shared__ __half smh[];
    __half* H16 = smh;
    __half* K16 = smh + 192 * 72;
    __half* V16 = smh + 2 * 192 * 72;
    __half* W16 = smh + 3 * 192 * 72;

    int b = blockIdx.x / 12, h = blockIdx.x % 12;
    int tid = threadIdx.x, lane = tid & 31, w = tid >> 5;
    int g4 = lane >> 2, c4 = lane & 3;
    int lmrow = lane & 15, lmk = (lane >> 4) * 8;
    int m4 = lane >> 3, r8 = lane & 7;
    int xrow = ((m4 >> 1) << 3) + r8, xk = (m4 & 1) * 8;
    int trow = m4 * 8 + r8;
    const int r0 = w * 16;

    {
        const __half* qsrc = qh + (long)h * 12288;
        for (int idx = tid; idx < 192 * 8; idx += 384) {
            int row = idx >> 3, q = idx & 7;
            *(uint4*)&W16[row * 72 + q * 8] = *(const uint4*)(qsrc + row * 64 + q * 8);
        }
    }
    {
        const __half* hb = h16g + (long)b * 180 * 64;
        for (int idx = tid; idx < 180 * 8; idx += 384) {
            int row = idx >> 3, q = idx & 7;
            *(uint4*)&H16[row * 72 + q * 8] = *(const uint4*)(hb + row * 64 + q * 8);
        }
        for (int i = tid; i < 12 * 72; i += 384) H16[180 * 72 + i] = __float2half(0.f);
    }
    __syncthreads();

    uint32_t afr[4][4];
#pragma unroll
    for (int ks = 0; ks < 4; ks++)
        ldsm_x4(afr[ks], smem_u32(&H16[(r0 + lmrow) * 72 + ks * 16 + lmk]));

#pragma unroll
    for (int mat = 0; mat < 2; mat++) {
        const __half* Wm = W16 + mat * 64 * 72;
        __half* dst = mat ? V16 : K16;
#pragma unroll
        for (int ntp = 0; ntp < 4; ntp++) {
            float a0[4] = {0.f, 0.f, 0.f, 0.f}, a1[4] = {0.f, 0.f, 0.f, 0.f};
#pragma unroll
            for (int ks = 0; ks < 4; ks++) {
                uint32_t bf4[4];
                ldsm_x4(bf4, smem_u32(&Wm[(ntp * 16 + xrow) * 72 + ks * 16 + xk]));
                mma_f16(a0, afr[ks], bf4, a0);
                mma_f16(a1, afr[ks], bf4 + 2, a1);
            }
            int col0 = (2 * ntp) * 8 + 2 * c4, col1 = col0 + 8;
            *(uint32_t*)&dst[(r0 + g4) * 72 + col0]     = packh2(a0[0], a0[1]);
            *(uint32_t*)&dst[(r0 + g4 + 8) * 72 + col0] = packh2(a0[2], a0[3]);
            *(uint32_t*)&dst[(r0 + g4) * 72 + col1]     = packh2(a1[0], a1[1]);
            *(uint32_t*)&dst[(r0 + g4 + 8) * 72 + col1] = packh2(a1[2], a1[3]);
        }
    }

    uint32_t afq[4][4];
    {
        const __half* Wm = W16 + 2 * 64 * 72;
        float qacc[8][4];
#pragma unroll
        for (int ntp = 0; ntp < 4; ntp++) {
#pragma unroll
            for (int i = 0; i < 4; i++) { qacc[2 * ntp][i] = 0.f; qacc[2 * ntp + 1][i] = 0.f; }
#pragma unroll
            for (int ks = 0; ks < 4; ks++) {
                uint32_t bf4[4];
                ldsm_x4(bf4, smem_u32(&Wm[(ntp * 16 + xrow) * 72 + ks * 16 + xk]));
                mma_f16(qacc[2 * ntp], afr[ks], bf4, qacc[2 * ntp]);
                mma_f16(qacc[2 * ntp + 1], afr[ks], bf4 + 2, qacc[2 * ntp + 1]);
            }
        }
#pragma unroll
        for (int kt = 0; kt < 4; kt++) {
            afq[kt][0] = packh2(qacc[2 * kt][0],     qacc[2 * kt][1]);
            afq[kt][1] = packh2(qacc[2 * kt][2],     qacc[2 * kt][3]);
            afq[kt][2] = packh2(qacc[2 * kt + 1][0], qacc[2 * kt + 1][1]);
            afq[kt][3] = packh2(qacc[2 * kt + 1][2], qacc[2 * kt + 1][3]);
        }
    }
    __syncthreads();

    float S[24][4];
#pragma unroll
    for (int ntp = 0; ntp < 12; ntp++) {
        float a0[4] = {0.f, 0.f, 0.f, 0.f}, a1[4] = {0.f, 0.f, 0.f, 0.f};
#pragma unroll
        for (int ks = 0; ks < 4; ks++) {
            uint32_t bf4[4];
            ldsm_x4(bf4, smem_u32(&K16[(ntp * 16 + xrow) * 72 + ks * 16 + xk]));
            mma_f16(a0, afq[ks], bf4, a0);
            mma_f16(a1, afq[ks], bf4 + 2, a1);
        }
#pragma unroll
        for (int i = 0; i < 4; i++) {
            S[2 * ntp][i]     = a0[i] * 0.125f;
            S[2 * ntp + 1][i] = a1[i] * 0.125f;
        }
    }

    {
        float mx0 = -1e30f, mx1 = -1e30f;
#pragma unroll
        for (int nt = 0; nt < 24; nt++) {
#pragma unroll
            for (int j = 0; j < 2; j++) {
                int col = nt * 8 + 2 * c4 + j;
                if (col < 180) {
                    mx0 = fmaxf(mx0, S[nt][j]);
                    mx1 = fmaxf(mx1, S[nt][2 + j]);
                }
            }
        }
        mx0 = fmaxf(mx0, __shfl_xor_sync(0xffffffffu, mx0, 1));
        mx0 = fmaxf(mx0, __shfl_xor_sync(0xffffffffu, mx0, 2));
        mx1 = fmaxf(mx1, __shfl_xor_sync(0xffffffffu, mx1, 1));
        mx1 = fmaxf(mx1, __shfl_xor_sync(0xffffffffu, mx1, 2));
        float sum0 = 0.f, sum1 = 0.f;
#pragma unroll
        for (int nt = 0; nt < 24; nt++) {
#pragma unroll
            for (int j = 0; j < 2; j++) {
                int col = nt * 8 + 2 * c4 + j;
                float e0 = (col < 180) ? __expf(S[nt][j] - mx0) : 0.f;
                float e1 = (col < 180) ? __expf(S[nt][2 + j] - mx1) : 0.f;
                S[nt][j] = e0; S[nt][2 + j] = e1;
                sum0 += e0; sum1 += e1;
            }
        }
        sum0 += __shfl_xor_sync(0xffffffffu, sum0, 1);
        sum0 += __shfl_xor_sync(0xffffffffu, sum0, 2);
        sum1 += __shfl_xor_sync(0xffffffffu, sum1, 1);
        sum1 += __shfl_xor_sync(0xffffffffu, sum1, 2);
        float inv0 = 1.f / sum0, inv1 = 1.f / sum1;
#pragma unroll
        for (int nt = 0; nt < 24; nt++) {
            S[nt][0] *= inv0; S[nt][1] *= inv0;
            S[nt][2] *= inv1; S[nt][3] *= inv1;
        }
    }

    uint32_t P[12][4];
#pragma unroll
    for (int kt = 0; kt < 12; kt++) {
        P[kt][0] = packh2(S[2 * kt][0],     S[2 * kt][1]);
        P[kt][1] = packh2(S[2 * kt][2],     S[2 * kt][3]);
        P[kt][2] = packh2(S[2 * kt + 1][0], S[2 * kt + 1][1]);
        P[kt][3] = packh2(S[2 * kt + 1][2], S[2 * kt + 1][3]);
    }

    {
        __half* outb = out + (long)b * 180 * 768 + h * 64;
#pragma unroll
        for (int nt = 0; nt < 8; nt++) {
            float acc[4] = {0.f, 0.f, 0.f, 0.f};
#pragma unroll
            for (int ktp = 0; ktp < 6; ktp++) {
                uint32_t bv4[4];
                ldsm_x4t(bv4, smem_u32(&V16[(ktp * 32 + trow) * 72 + nt * 8]));
                mma_f16(acc, P[2 * ktp], bv4, acc);
                mma_f16(acc, P[2 * ktp + 1], bv4 + 2, acc);
            }
            int row = r0 + g4;
            long col = nt * 8 + 2 * c4;
            if (row < 180)
                *(uint32_t*)(outb + (long)row * 768 + col) = packh2(acc[0], acc[1]);
            if (row + 8 < 180)
                *(uint32_t*)(outb + (long)(row + 8) * 768 + col) = packh2(acc[2], acc[3]);
        }
    }
}

// ---------------- fused tail (x4 ldsm): outproj + LN2 + MLP + next LN1 ----------------
#define T_WS   0
#define T_ASHS 49664
#define T_W1S  58880
#define T_W2S  77312
#define TAIL_SMEM 188416

__global__ void __launch_bounds__(256) tail_fused_k(const __half* __restrict__ ao,
                                                    const __half* __restrict__ owh,
                                                    const float* __restrict__ ob,
                                                    const float* __restrict__ x,
                                                    const __half* __restrict__ w1h,
                                                    const float* __restrict__ b1,
                                                    const __half* __restrict__ w2h,
                                                    const float* __restrict__ b2,
                                                    const float* __restrict__ lng,
                                                    const float* __restrict__ lnb,
                                                    float* __restrict__ outx,
                                                    const float* __restrict__ lng1n,
                                                    const float* __restrict__ lnb1n,
                                                    __half* __restrict__ h16out) {
    extern __shared__ __half smt[];
    __half* Ws  = smt + T_WS;
    __half* As  = smt + T_ASHS;
    __half* W1s = smt + T_W1S;
    __half* W2s = smt + T_W2S;

    const int tid = threadIdx.x, lane = tid & 31, w = tid >> 5;
    const int g4 = lane >> 2, c4 = lane & 3;
    const int lmrow = lane & 15, lmk = (lane >> 4) * 8;
    const int m4 = lane >> 3, r8 = lane & 7;
    const int xrow = ((m4 >> 1) << 3) + r8, xk = (m4 & 1) * 8;
    const int r0 = w * 16;

    for (int idx = tid; idx < 64 * 96; idx += 256) {
        int n = idx / 96, q = idx % 96;
        *(uint4*)&Ws[n * 776 + q * 8] = *(const uint4*)(owh + n * 768 + q * 8);
    }
    for (int idx = tid; idx < 256 * 8; idx += 256) {
        int n = idx >> 3, q = idx & 7;
        *(uint4*)&W1s[n * 72 + q * 8] = *(const uint4*)(w1h + n * 64 + q * 8);
    }
    for (int idx = tid; idx < 64 * 32; idx += 256) {
        int n = idx >> 5, q = idx & 31;
        *(uint4*)&W2s[n * 264 + q * 8] = *(const uint4*)(w2h + n * 256 + q * 8);
    }
    __syncthreads();

    const int ar = tid >> 1, apart = (tid & 1) * 32;

    for (int c = 0; c < 3; c++) {
        const long bm = ((long)blockIdx.x * 3 + c) * 128;

        float acc[8][4];
#pragma unroll
        for (int nt = 0; nt < 8; nt++)
#pragma unroll
            for (int i = 0; i < 4; i++) acc[nt][i] = 0.f;

        for (int kc = 0; kc < 12; kc++) {
            {
                const uint4* src = (const uint4*)(ao + (bm + ar) * 768 + kc * 64 + apart);
                uint4* dst = (uint4*)&As[ar * 72 + apart];
                dst[0] = src[0]; dst[1] = src[1]; dst[2] = src[2]; dst[3] = src[3];
            }
            __syncwarp();
            uint32_t afr[4][4];
#pragma unroll
            for (int ks = 0; ks < 4; ks++)
                ldsm_x4(afr[ks], smem_u32(&As[(r0 + lmrow) * 72 + ks * 16 + lmk]));
#pragma unroll
            for (int ntp = 0; ntp < 4; ntp++) {
#pragma unroll
                for (int ks = 0; ks < 4; ks++) {
                    uint32_t bf4[4];
                    ldsm_x4(bf4, smem_u32(&Ws[(ntp * 16 + xrow) * 776 + kc * 64 + ks * 16 + xk]));
                    mma_f16(acc[2 * ntp], afr[ks], bf4, acc[2 * ntp]);
                    mma_f16(acc[2 * ntp + 1], afr[ks], bf4 + 2, acc[2 * ntp + 1]);
                }
            }
            __syncwarp();
        }

        float xres[8][4];
#pragma unroll
        for (int nt = 0; nt < 8; nt++) {
            int col = nt * 8 + 2 * c4;
            float b0 = ob[col], b1v = ob[col + 1];
#pragma unroll
            for (int half = 0; half < 2; half++) {
                long row = bm + r0 + g4 + 8 * half;
                float2 r = *(const float2*)(x + row * 64 + col);
                xres[nt][2 * half]     = acc[nt][2 * half] + b0 + r.x;
                xres[nt][2 * half + 1] = acc[nt][2 * half + 1] + b1v + r.y;
            }
        }
        {
            float s0 = 0.f, s1 = 0.f;
#pragma unroll
            for (int nt = 0; nt < 8; nt++) {
                s0 += xres[nt][0] + xres[nt][1];
                s1 += xres[nt][2] + xres[nt][3];
            }
            s0 += __shfl_xor_sync(0xffffffffu, s0, 1);
            s0 += __shfl_xor_sync(0xffffffffu, s0, 2);
            s1 += __shfl_xor_sync(0xffffffffu, s1, 1);
            s1 += __shfl_xor_sync(0xffffffffu, s1, 2);
            float m0 = s0 * (1.f / 64.f), m1 = s1 * (1.f / 64.f);
            float q0 = 0.f, q1 = 0.f;
#pragma unroll
            for (int nt = 0; nt < 8; nt++) {
                float d0 = xres[nt][0] - m0, d1 = xres[nt][1] - m0;
                float d2 = xres[nt][2] - m1, d3 = xres[nt][3] - m1;
                q0 += d0 * d0 + d1 * d1;
                q1 += d2 * d2 + d3 * d3;
            }
            q0 += __shfl_xor_sync(0xffffffffu, q0, 1);
            q0 += __shfl_xor_sync(0xffffffffu, q0, 2);
            q1 += __shfl_xor_sync(0xffffffffu, q1, 1);
            q1 += __shfl_xor_sync(0xffffffffu, q1, 2);
            float rs0 = rsqrtf(q0 * (1.f / 64.f) + 1e-5f);
            float rs1 = rsqrtf(q1 * (1.f / 64.f) + 1e-5f);
#pragma unroll
            for (int nt = 0; nt < 8; nt++) {
                int col = nt * 8 + 2 * c4;
                float g0 = lng[col], g1 = lng[col + 1];
                float be0 = lnb[col], be1 = lnb[col + 1];
                float h0 = (xres[nt][0] - m0) * rs0 * g0 + be0;
                float h1 = (xres[nt][1] - m0) * rs0 * g1 + be1;
                float h2 = (xres[nt][2] - m1) * rs1 * g0 + be0;
                float h3 = (xres[nt][3] - m1) * rs1 * g1 + be1;
                *(uint32_t*)&As[(r0 + g4) * 72 + col]     = packh2(h0, h1);
                *(uint32_t*)&As[(r0 + g4 + 8) * 72 + col] = packh2(h2, h3);
            }
        }
        __syncwarp();

        uint32_t afg[16][4];
        {
            uint32_t afr[4][4];
#pragma unroll
            for (int ks = 0; ks < 4; ks++)
                ldsm_x4(afr[ks], smem_u32(&As[(r0 + lmrow) * 72 + ks * 16 + lmk]));
#pragma unroll
            for (int kt = 0; kt < 16; kt++) {
                float d0[4] = {0.f, 0.f, 0.f, 0.f}, d1[4] = {0.f, 0.f, 0.f, 0.f};
#pragma unroll
                for (int ks = 0; ks < 4; ks++) {
                    uint32_t bf4[4];
                    ldsm_x4(bf4, smem_u32(&W1s[(kt * 16 + xrow) * 72 + ks * 16 + xk]));
                    mma_f16(d0, afr[ks], bf4, d0);
                    mma_f16(d1, afr[ks], bf4 + 2, d1);
                }
                int col0 = (2 * kt) * 8 + 2 * c4, col1 = (2 * kt + 1) * 8 + 2 * c4;
                float a0 = d0[0] + b1[col0],     a1 = d0[1] + b1[col0 + 1];
                float a2 = d0[2] + b1[col0],     a3 = d0[3] + b1[col0 + 1];
                float a4 = d1[0] + b1[col1],     a5 = d1[1] + b1[col1 + 1];
                float a6 = d1[2] + b1[col1],     a7 = d1[3] + b1[col1 + 1];
                a0 = 0.5f * a0 * (1.f + erff(a0 * 0.70710678118654752f));
                a1 = 0.5f * a1 * (1.f + erff(a1 * 0.70710678118654752f));
                a2 = 0.5f * a2 * (1.f + erff(a2 * 0.70710678118654752f));
                a3 = 0.5f * a3 * (1.f + erff(a3 * 0.70710678118654752f));
                a4 = 0.5f * a4 * (1.f + erff(a4 * 0.70710678118654752f));
                a5 = 0.5f * a5 * (1.f + erff(a5 * 0.70710678118654752f));
                a6 = 0.5f * a6 * (1.f + erff(a6 * 0.70710678118654752f));
                a7 = 0.5f * a7 * (1.f + erff(a7 * 0.70710678118654752f));
                afg[kt][0] = packh2(a0, a1);
                afg[kt][1] = packh2(a2, a3);
                afg[kt][2] = packh2(a4, a5);
                afg[kt][3] = packh2(a6, a7);
            }
        }

        float xf[8][4];
#pragma unroll
        for (int nt = 0; nt < 8; nt++) {
            float a2c[4] = {0.f, 0.f, 0.f, 0.f};
#pragma unroll
            for (int ktp = 0; ktp < 8; ktp++) {
                uint32_t bf4[4];
                ldsm_x4(bf4, smem_u32(&W2s[(nt * 8 + r8) * 264 + ktp * 32 + m4 * 8]));
                mma_f16(a2c, afg[2 * ktp], bf4, a2c);
                mma_f16(a2c, afg[2 * ktp + 1], bf4 + 2, a2c);
            }
            int col = nt * 8 + 2 * c4;
            float bb0 = b2[col], bb1 = b2[col + 1];
#pragma unroll
            for (int half = 0; half < 2; half++) {
                long row = bm + r0 + g4 + 8 * half;
                float v0 = a2c[2 * half] + bb0 + xres[nt][2 * half];
                float v1 = a2c[2 * half + 1] + bb1 + xres[nt][2 * half + 1];
                xf[nt][2 * half] = v0; xf[nt][2 * half + 1] = v1;
                *(float2*)(outx + row * 64 + col) = make_float2(v0, v1);
            }
        }
        if (h16out) {
            float s0 = 0.f, s1 = 0.f;
#pragma unroll
            for (int nt = 0; nt < 8; nt++) {
                s0 += xf[nt][0] + xf[nt][1];
                s1 += xf[nt][2] + xf[nt][3];
            }
            s0 += __shfl_xor_sync(0xffffffffu, s0, 1);
            s0 += __shfl_xor_sync(0xffffffffu, s0, 2);
            s1 += __shfl_xor_sync(0xffffffffu, s1, 1);
            s1 += __shfl_xor_sync(0xffffffffu, s1, 2);
            float m0 = s0 * (1.f / 64.f), m1 = s1 * (1.f / 64.f);
            float q0 = 0.f, q1 = 0.f;
#pragma unroll
            for (int nt = 0; nt < 8; nt++) {
                float d0 = xf[nt][0] - m0, d1 = xf[nt][1] - m0;
                float d2 = xf[nt][2] - m1, d3 = xf[nt][3] - m1;
                q0 += d0 * d0 + d1 * d1;
                q1 += d2 * d2 + d3 * d3;
            }
            q0 += __shfl_xor_sync(0xffffffffu, q0, 1);
            q0 += __shfl_xor_sync(0xffffffffu, q0, 2);
            q1 += __shfl_xor_sync(0xffffffffu, q1, 1);
            q1 += __shfl_xor_sync(0xffffffffu, q1, 2);
            float rs0 = rsqrtf(q0 * (1.f / 64.f) + 1e-5f);
            float rs1 = rsqrtf(q1 * (1.f / 64.f) + 1e-5f);
#pragma unroll
            for (int nt = 0; nt < 8; nt++) {
                int col = nt * 8 + 2 * c4;
                float g0 = lng1n[col], g1 = lng1n[col + 1];
                float be0 = lnb1n[col], be1 = lnb1n[col + 1];
                long row0g = bm + r0 + g4;
                *(uint32_t*)(h16out + row0g * 64 + col) =
                    packh2((xf[nt][0] - m0) * rs0 * g0 + be0, (xf[nt][1] - m0) * rs0 * g1 + be1);
                *(uint32_t*)(h16out + (row0g + 8) * 64 + col) =
                    packh2((xf[nt][2] - m1) * rs1 * g0 + be0, (xf[nt][3] - m1) * rs1 * g1 + be1);
            }
        }
        __syncwarp();
    }
}

// ---------------- fused squash + capsule predictions (fp16 out) ----------------
__global__ void caps_usq_k(const float* __restrict__ pc, const float* __restrict__ cw,
                           __half* __restrict__ u) {
    __shared__ float w_s[8 * 48];
    int i = blockIdx.x;
    for (int t = threadIdx.x; t < 384; t += 256) w_s[t] = cw[(long)i * 384 + t];
    __syncthreads();
    int b = threadIdx.x;
    int i32 = i >> 5, y = (i >> 3) & 3, xq = i & 7;
    const float* src = pc + (((long)b * 4 + y) * 8 + xq) * 256 + i32 * 8;
    float ce[8];
    float l2 = 0.f;
#pragma unroll
    for (int e = 0; e < 8; e++) { ce[e] = src[e]; l2 += ce[e] * ce[e]; }
    float sc = sqrtf(l2) / (1.f + l2);
#pragma unroll
    for (int e = 0; e < 8; e++) ce[e] *= sc;
    __half* up = u + ((long)b * 1024 + i) * 48;
#pragma unroll 4
    for (int o = 0; o < 48; o++) {
        float s = 0.f;
#pragma unroll
        for (int e = 0; e < 8; e++) s = fmaf(ce[e], w_s[e * 48 + o], s);
        up[o] = __float2half(s);
    }
}

// ---------------- dynamic routing ----------------
#define ROUT_SMEM ((49152 + 3072 + 96) * 4)
__global__ void __launch_bounds__(256) routing_k(const __half* __restrict__ u,
                                                 const float* __restrict__ br,
                                                 float* __restrict__ out) {
    extern __shared__ float smr[];
    float* us = smr;
    float* bb = smr + 49152;
    float* S  = bb + 3072;
    float* v  = S + 48;
    int b = blockIdx.x, tid = threadIdx.x, lane = tid & 31;
    const __half* ub = u + (long)b * 1024 * 48;
    for (int i = tid; i < 49152; i += 256) us[i] = __half2float(ub[i]);
    for (int i = tid; i < 3072; i += 256) bb[i] = br[i];
    __syncthreads();

    for (int it = 0; it < 4; it++) {
        if (tid < 48) S[tid] = 0.f;
        __syncthreads();
        float acc[48];
#pragma unroll
        for (int o = 0; o < 48; o++) acc[o] = 0.f;
        for (int i = tid; i < 1024; i += 256) {
            float b0 = bb[i * 3], b1 = bb[i * 3 + 1], b2 = bb[i * 3 + 2];
            float m = fmaxf(b0, fmaxf(b1, b2));
            float e0 = expf(b0 - m), e1 = expf(b1 - m), e2 = expf(b2 - m);
            float inv = 1.f / (e0 + e1 + e2);
            float c[3] = {e0 * inv, e1 * inv, e2 * inv};
            const float* up = &us[i * 48];
#pragma unroll
            for (int j = 0; j < 3; j++)
#pragma unroll
                for (int o = 0; o < 16; o++)
                    acc[j * 16 + o] = fmaf(c[j], up[j * 16 + o], acc[j * 16 + o]);
        }
#pragma unroll
        for (int o = 0; o < 48; o++) {
            float s = acc[o];
#pragma unroll
            for (int d = 16; d; d >>= 1) s += __shfl_xor_sync(0xffffffffu, s, d);
            if (lane == 0) atomicAdd(&S[o], s);
        }
        __syncthreads();
        if (tid < 3) {
            float l2 = 0.f;
            for (int o = 0; o < 16; o++) { float t = S[tid * 16 + o]; l2 += t * t; }
            float sc = sqrtf(l2) / (1.f + l2);
            for (int o = 0; o < 16; o++) v[tid * 16 + o] = S[tid * 16 + o] * sc;
            if (it == 3) out[b * 3 + tid] = l2 / (1.f + l2);
        }
        __syncthreads();
        if (it < 3) {
            for (int i = tid; i < 1024; i += 256) {
                const float* up = &us[i * 48];
#pragma unroll
                for (int j = 0; j < 3; j++) {
                    float s = 0.f;
#pragma unroll
                    for (int o = 0; o < 16; o++) s = fmaf(up[j * 16 + o], v[j * 16 + o], s);
                    bb[i * 3 + j] += s;
                }
            }
            __syncthreads();
        }
    }
}

// ---------------- host ----------------
extern "C" void kernel_launch(void* const* d_in, const int* in_sizes, int n_in,
                              void* d_out, int out_size) {
    const float* x_in    = (const float*)d_in[0];
    const float* conv1_w = (const float*)d_in[1];
    const float* conv2_w = (const float*)d_in[2];
    const float* pos_emb = (const float*)d_in[3];
    const float* ln1_g   = (const float*)d_in[4];
    const float* ln1_b   = (const float*)d_in[5];
    const float* qkv_w   = (const float*)d_in[6];
    const float* out_w   = (const float*)d_in[7];
    const float* out_b   = (const float*)d_in[8];
    const float* ln2_g   = (const float*)d_in[9];
    const float* ln2_b   = (const float*)d_in[10];
    const float* ff1_w   = (const float*)d_in[11];
    const float* ff1_b   = (const float*)d_in[12];
    const float* ff2_w   = (const float*)d_in[13];
    const float* ff2_b   = (const float*)d_in[14];
    const float* pcaps_w = (const float*)d_in[15];
    const float* pcaps_b = (const float*)d_in[16];
    const float* caps_w  = (const float*)d_in[17];
    const float* b_route = (const float*)d_in[18];
    float* out = (float*)d_out;

    float *xb, *col3, *wtp, *pc;
    __half *y1h, *p1h, *y2h, *h16g, *aoh, *uh, *qh, *owh, *w1h, *w2h, *cw1h, *cw2h;
    cudaGetSymbolAddress((void**)&y1h,  g_y1h);
    cudaGetSymbolAddress((void**)&p1h,  g_p1h);
    cudaGetSymbolAddress((void**)&y2h,  g_y2h);
    cudaGetSymbolAddress((void**)&xb,   g_x);
    cudaGetSymbolAddress((void**)&h16g, g_h16);
    cudaGetSymbolAddress((void**)&aoh,  g_aoh);
    cudaGetSymbolAddress((void**)&col3, g_col3);
    cudaGetSymbolAddress((void**)&wtp,  g_wtp);
    cudaGetSymbolAddress((void**)&pc,   g_pc);
    cudaGetSymbolAddress((void**)&uh,   g_uh);
    cudaGetSymbolAddress((void**)&qh,   g_qh);
    cudaGetSymbolAddress((void**)&owh,  g_owh);
    cudaGetSymbolAddress((void**)&w1h,  g_w1h);
    cudaGetSymbolAddress((void**)&w2h,  g_w2h);
    cudaGetSymbolAddress((void**)&cw1h, g_cw1h);
    cudaGetSymbolAddress((void**)&cw2h, g_cw2h);

    cudaFuncSetAttribute(attn_fused_k, cudaFuncAttributeMaxDynamicSharedMemorySize, ATTNH_SMEM);
    cudaFuncSetAttribute(tail_fused_k, cudaFuncAttributeMaxDynamicSharedMemorySize, TAIL_SMEM);
    cudaFuncSetAttribute(hconv1d_k,    cudaFuncAttributeMaxDynamicSharedMemorySize, HC1_SMEM);
    cudaFuncSetAttribute(hconv2_k,     cudaFuncAttributeMaxDynamicSharedMemorySize, HC2_SMEM);
    cudaFuncSetAttribute(routing_k,    cudaFuncAttributeMaxDynamicSharedMemorySize, ROUT_SMEM);

    prep_qkv_k<<<CDIV(12 * 12 * 3 * 4096, 256), 256>>>(qkv_w, qh);
    prep_ow_k <<<CDIV(12 * 64 * 768, 256), 256>>>(out_w, owh);
    prep_w1_k <<<CDIV(12 * 256 * 64, 256), 256>>>(ff1_w, w1h);
    prep_w2_k <<<CDIV(12 * 64 * 256, 256), 256>>>(ff2_w, w2h);
    prep_cw1_k<<<CDIV(64 * 32, 256), 256>>>(conv1_w, cw1h);
    prep_cw2_k<<<CDIV(64 * 576, 256), 256>>>(conv2_w, cw2h);

    // ---- ConvEmbed (fp16 MMA, direct conv1 + half2 pools) ----
    hconv1d_k<<<737280 / 128, 256, HC1_SMEM>>>(x_in, cw1h, y1h);
    maxpool_h2_k<<<(int)CDIV((long)256 * 20 * 36 * 32, 256), 256>>>(
        (const __half2*)y1h, (__half2*)p1h, 256, 40, 72, 20, 36);
    hconv2_k<<<184320 / 128, 256, HC2_SMEM>>>(p1h, cw2h, y2h);
    maxpool_h2f_k<<<(int)CDIV((long)256 * 10 * 18 * 32, 256), 256>>>(
        (const __half2*)y2h, xb, 256, 20, 36, 10, 18, pos_emb);

    // ---- Transformer: 12 shared layers applied twice, LN1 fused into tail ----
    const int M = 46080;
    ln1h_k<<<M / 8, 256>>>(xb, ln1_g, ln1_b, h16g, M);
    for (int pass = 0; pass < 2; pass++) {
        for (int l = 0; l < 12; l++) {
            bool last = (pass == 1) && (l == 11);
            int ln = (l + 1) % 12;
            attn_fused_k<<<256 * 12, 384, ATTNH_SMEM>>>(h16g, qh + (long)l * 147456, aoh);
            tail_fused_k<<<120, 256, TAIL_SMEM>>>(aoh, owh + (long)l * 49152, out_b + l * 64,
                                                  xb, w1h + (long)l * 16384, ff1_b + l * 256,
                                                  w2h + (long)l * 16384, ff2_b + l * 64,
                                                  ln2_g + l * 64, ln2_b + l * 64, xb,
                                                  last ? nullptr : ln1_g + ln * 64,
                                                  last ? nullptr : ln1_b + ln * 64,
                                                  last ? nullptr : h16g);
        }
    }

    // ---- PrimaryCaps + routing ----
    im2col3_k<<<(int)CDIV((long)8192 * 576, 256), 256>>>(xb, col3);
    wtrans_hwc<<<CDIV(256 * 576, 256), 256>>>(pcaps_w, wtp, 256, 64);
    tgemm_k<2><<<dim3(256 / 64, 8192 / 128), 256>>>(col3, wtp, pcaps_b, pc, 8192, 256, 576);
    caps_usq_k<<<1024, 256>>>(pc, caps_w, uh);
    routing_k<<<256, 256, ROUT_SMEM>>>(uh, b_route, out);
}